// round 1
// baseline (speedup 1.0000x reference)
#include <cuda_runtime.h>
#include <math.h>

#define S_LEN 2048
#define BATCH 2
#define EMB   2048
#define NH    16
#define NKV   4
#define HD    128
#define KVDIM (NKV*HD)        // 512
#define MROWS (BATCH*S_LEN)   // 4096

#define QT 64
#define KT 64
#define KSTRIDE 68            // padded stride for transposed K (16B-aligned, conflict-free)
#define PST 65                // padded stride for score tile

// Scratch (allocation-free per harness rules)
__device__ float g_q[(size_t)MROWS * EMB];
__device__ float g_k[(size_t)MROWS * KVDIM];
__device__ float g_v[(size_t)MROWS * KVDIM];
__device__ float g_attn[(size_t)MROWS * EMB];

// ----------------------------------------------------------------------------
// C[M,N] = A[M,K] @ B[N,K]^T   (row-major A and B; "NT" gemm)
// 128x128 block tile, BK=8, 256 threads, 8x8 per-thread microtile.
// Requires M%128==0, N%128==0, K%8==0 (true for all shapes here).
// ----------------------------------------------------------------------------
__global__ __launch_bounds__(256) void sgemm_nt(const float* __restrict__ A,
                                                const float* __restrict__ B,
                                                float* __restrict__ C,
                                                int M, int N, int K)
{
    __shared__ float As[8][128];
    __shared__ float Bs[8][128];

    const int tid  = threadIdx.x;
    const int brow = blockIdx.y * 128;
    const int bcol = blockIdx.x * 128;
    const int trow = (tid >> 4) * 8;      // 0..120
    const int tcol = (tid & 15) * 8;      // 0..120
    const int lr   = tid >> 1;            // 0..127
    const int lc   = (tid & 1) * 4;       // 0 or 4

    const float* Aptr = A + (size_t)(brow + lr) * K + lc;
    const float* Bptr = B + (size_t)(bcol + lr) * K + lc;

    float acc[8][8];
    #pragma unroll
    for (int i = 0; i < 8; i++)
        #pragma unroll
        for (int j = 0; j < 8; j++) acc[i][j] = 0.f;

    for (int k0 = 0; k0 < K; k0 += 8) {
        float4 a4 = *(const float4*)(Aptr + k0);
        float4 b4 = *(const float4*)(Bptr + k0);
        As[lc+0][lr] = a4.x; As[lc+1][lr] = a4.y; As[lc+2][lr] = a4.z; As[lc+3][lr] = a4.w;
        Bs[lc+0][lr] = b4.x; Bs[lc+1][lr] = b4.y; Bs[lc+2][lr] = b4.z; Bs[lc+3][lr] = b4.w;
        __syncthreads();

        #pragma unroll
        for (int k = 0; k < 8; k++) {
            float ar[8], br[8];
            *(float4*)&ar[0] = *(const float4*)&As[k][trow];
            *(float4*)&ar[4] = *(const float4*)&As[k][trow + 4];
            *(float4*)&br[0] = *(const float4*)&Bs[k][tcol];
            *(float4*)&br[4] = *(const float4*)&Bs[k][tcol + 4];
            #pragma unroll
            for (int i = 0; i < 8; i++)
                #pragma unroll
                for (int j = 0; j < 8; j++)
                    acc[i][j] += ar[i] * br[j];
        }
        __syncthreads();
    }

    #pragma unroll
    for (int i = 0; i < 8; i++) {
        float* crow = C + (size_t)(brow + trow + i) * N + bcol + tcol;
        *(float4*)(crow + 0) = *(float4*)&acc[i][0];
        *(float4*)(crow + 4) = *(float4*)&acc[i][4];
    }
}

// ----------------------------------------------------------------------------
// Flash attention, causal, GQA (rep = NH/NKV = 4).
// Grid: (S/64 q-tiles, NH, BATCH). Block: 256 threads.
// Q tile 64x128 in smem (pre-scaled). Per kv tile: K^T into smem, scores,
// online softmax, V into same buffer, O += P*V (O in regs, 4 rows x 8 cols
// per thread).
// ----------------------------------------------------------------------------
__global__ __launch_bounds__(256) void attn_kernel()
{
    extern __shared__ float sm[];
    float* Qs     = sm;                          // 64*128       = 8192
    float* KV     = Qs + QT * HD;                // 128*68       = 8704 (K^T) / 64*128 (V)
    float* Ps     = KV + 128 * KSTRIDE;          // 64*65        = 4160
    float* row_m  = Ps + QT * PST;               // 64
    float* row_l  = row_m + QT;                  // 64
    float* row_cf = row_l + QT;                  // 64

    const int tid = threadIdx.x;
    const int iq  = blockIdx.x;
    const int h   = blockIdx.y;
    const int b   = blockIdx.z;
    const int kvh = h / (NH / NKV);
    const int tx  = tid & 15;
    const int ty  = tid >> 4;

    // --- load Q tile, pre-scaled by 1/sqrt(D) ---
    {
        const float scale = 0.08838834764831845f;  // 1/sqrt(128)
        const float* qg = g_q + ((size_t)(b * S_LEN + iq * QT)) * EMB + h * HD;
        #pragma unroll
        for (int it = 0; it < 8; it++) {
            int idx = it * 256 + tid;          // float4 index, 0..2047
            int r   = idx >> 5;                // 0..63
            int c4  = (idx & 31) * 4;          // 0..124
            float4 v = *(const float4*)(qg + (size_t)r * EMB + c4);
            float* dst = Qs + r * HD + c4;
            dst[0] = v.x * scale; dst[1] = v.y * scale;
            dst[2] = v.z * scale; dst[3] = v.w * scale;
        }
    }
    if (tid < QT) { row_m[tid] = -3.0e38f; row_l[tid] = 0.f; }

    float o[4][8];
    #pragma unroll
    for (int i = 0; i < 4; i++)
        #pragma unroll
        for (int j = 0; j < 8; j++) o[i][j] = 0.f;

    const float* kg_base = g_k + ((size_t)(b * S_LEN)) * KVDIM + kvh * HD;
    const float* vg_base = g_v + ((size_t)(b * S_LEN)) * KVDIM + kvh * HD;

    for (int jt = 0; jt <= iq; jt++) {
        __syncthreads();   // guard KV/Ps reuse from previous iteration

        // --- load K tile transposed: KV[d*KSTRIDE + t] = K[jt*64+t][d] ---
        {
            const float* kg = kg_base + (size_t)(jt * KT) * KVDIM;
            int t  = tid & 63;
            int dq = tid >> 6;   // 0..3
            #pragma unroll
            for (int rep = 0; rep < 8; rep++) {
                int d0 = (rep * 4 + dq) * 4;   // 0,4,...,124
                float4 k4 = *(const float4*)(kg + (size_t)t * KVDIM + d0);
                KV[(d0+0)*KSTRIDE + t] = k4.x;
                KV[(d0+1)*KSTRIDE + t] = k4.y;
                KV[(d0+2)*KSTRIDE + t] = k4.z;
                KV[(d0+3)*KSTRIDE + t] = k4.w;
            }
        }
        __syncthreads();

        // --- scores: sc[i][j] = sum_d Q[ty*4+i][d] * K^T[d][tx*4+j] ---
        float sc[4][4];
        #pragma unroll
        for (int i = 0; i < 4; i++)
            #pragma unroll
            for (int j = 0; j < 4; j++) sc[i][j] = 0.f;
        {
            const float* q0 = Qs + (ty*4 + 0) * HD;
            const float* q1 = Qs + (ty*4 + 1) * HD;
            const float* q2 = Qs + (ty*4 + 2) * HD;
            const float* q3 = Qs + (ty*4 + 3) * HD;
            for (int d0 = 0; d0 < HD; d0 += 4) {
                float4 a4 = *(const float4*)(q0 + d0);
                float4 b4 = *(const float4*)(q1 + d0);
                float4 c4 = *(const float4*)(q2 + d0);
                float4 e4 = *(const float4*)(q3 + d0);
                float qA[4] = {a4.x, a4.y, a4.z, a4.w};
                float qB[4] = {b4.x, b4.y, b4.z, b4.w};
                float qC[4] = {c4.x, c4.y, c4.z, c4.w};
                float qD[4] = {e4.x, e4.y, e4.z, e4.w};
                #pragma unroll
                for (int dd = 0; dd < 4; dd++) {
                    float4 k4 = *(const float4*)(KV + (d0 + dd) * KSTRIDE + tx * 4);
                    sc[0][0] += qA[dd]*k4.x; sc[0][1] += qA[dd]*k4.y;
                    sc[0][2] += qA[dd]*k4.z; sc[0][3] += qA[dd]*k4.w;
                    sc[1][0] += qB[dd]*k4.x; sc[1][1] += qB[dd]*k4.y;
                    sc[1][2] += qB[dd]*k4.z; sc[1][3] += qB[dd]*k4.w;
                    sc[2][0] += qC[dd]*k4.x; sc[2][1] += qC[dd]*k4.y;
                    sc[2][2] += qC[dd]*k4.z; sc[2][3] += qC[dd]*k4.w;
                    sc[3][0] += qD[dd]*k4.x; sc[3][1] += qD[dd]*k4.y;
                    sc[3][2] += qD[dd]*k4.z; sc[3][3] += qD[dd]*k4.w;
                }
            }
        }

        // --- causal mask + write score tile ---
        #pragma unroll
        for (int i = 0; i < 4; i++) {
            int r = ty * 4 + i;
            int sglob = iq * QT + r;
            #pragma unroll
            for (int j = 0; j < 4; j++) {
                int c = tx * 4 + j;
                float val = sc[i][j];
                if (jt * KT + c > sglob) val = -3.0e38f;
                Ps[r * PST + c] = val;
            }
        }
        __syncthreads();

        // --- online softmax, one thread per row ---
        if (tid < QT) {
            int r = tid;
            float m_old = row_m[r];
            float mx = m_old;
            for (int c = 0; c < KT; c++) mx = fmaxf(mx, Ps[r * PST + c]);
            float cf = __expf(m_old - mx);
            float l = row_l[r] * cf;
            for (int c = 0; c < KT; c++) {
                float p = __expf(Ps[r * PST + c] - mx);
                Ps[r * PST + c] = p;
                l += p;
            }
            row_m[r] = mx; row_l[r] = l; row_cf[r] = cf;
        }
        __syncthreads();

        // --- load V tile row-major into KV ---
        {
            const float* vg = vg_base + (size_t)(jt * KT) * KVDIM;
            #pragma unroll
            for (int it = 0; it < 8; it++) {
                int idx = it * 256 + tid;
                int r   = idx >> 5;
                int c4  = (idx & 31) * 4;
                *(float4*)(KV + r * HD + c4) =
                    *(const float4*)(vg + (size_t)r * KVDIM + c4);
            }
        }
        __syncthreads();

        // --- rescale O and accumulate O += P*V ---
        float cfr[4];
        #pragma unroll
        for (int i = 0; i < 4; i++) cfr[i] = row_cf[ty * 4 + i];
        #pragma unroll
        for (int i = 0; i < 4; i++)
            #pragma unroll
            for (int j = 0; j < 8; j++) o[i][j] *= cfr[i];

        for (int t = 0; t < KT; t++) {
            float p0 = Ps[(ty*4 + 0) * PST + t];
            float p1 = Ps[(ty*4 + 1) * PST + t];
            float p2 = Ps[(ty*4 + 2) * PST + t];
            float p3 = Ps[(ty*4 + 3) * PST + t];
            float4 va = *(const float4*)(KV + t * HD + tx * 8);
            float4 vb = *(const float4*)(KV + t * HD + tx * 8 + 4);
            o[0][0]+=p0*va.x; o[0][1]+=p0*va.y; o[0][2]+=p0*va.z; o[0][3]+=p0*va.w;
            o[0][4]+=p0*vb.x; o[0][5]+=p0*vb.y; o[0][6]+=p0*vb.z; o[0][7]+=p0*vb.w;
            o[1][0]+=p1*va.x; o[1][1]+=p1*va.y; o[1][2]+=p1*va.z; o[1][3]+=p1*va.w;
            o[1][4]+=p1*vb.x; o[1][5]+=p1*vb.y; o[1][6]+=p1*vb.z; o[1][7]+=p1*vb.w;
            o[2][0]+=p2*va.x; o[2][1]+=p2*va.y; o[2][2]+=p2*va.z; o[2][3]+=p2*va.w;
            o[2][4]+=p2*vb.x; o[2][5]+=p2*vb.y; o[2][6]+=p2*vb.z; o[2][7]+=p2*vb.w;
            o[3][0]+=p3*va.x; o[3][1]+=p3*va.y; o[3][2]+=p3*va.z; o[3][3]+=p3*va.w;
            o[3][4]+=p3*vb.x; o[3][5]+=p3*vb.y; o[3][6]+=p3*vb.z; o[3][7]+=p3*vb.w;
        }
    }

    // --- epilogue: normalize and write ---
    float invl[4];
    #pragma unroll
    for (int i = 0; i < 4; i++) invl[i] = 1.f / row_l[ty * 4 + i];
    float* og = g_attn + ((size_t)(b * S_LEN + iq * QT)) * EMB + h * HD;
    #pragma unroll
    for (int i = 0; i < 4; i++) {
        float* orow = og + (size_t)(ty * 4 + i) * EMB + tx * 8;
        float4 r0, r1;
        r0.x = o[i][0]*invl[i]; r0.y = o[i][1]*invl[i];
        r0.z = o[i][2]*invl[i]; r0.w = o[i][3]*invl[i];
        r1.x = o[i][4]*invl[i]; r1.y = o[i][5]*invl[i];
        r1.z = o[i][6]*invl[i]; r1.w = o[i][7]*invl[i];
        *(float4*)(orow + 0) = r0;
        *(float4*)(orow + 4) = r1;
    }
}

// ----------------------------------------------------------------------------
// Launch
// ----------------------------------------------------------------------------
extern "C" void kernel_launch(void* const* d_in, const int* in_sizes, int n_in,
                              void* d_out, int out_size)
{
    const float* x  = (const float*)d_in[0];
    const float* Wq = (const float*)d_in[1];
    const float* Wk = (const float*)d_in[2];
    const float* Wv = (const float*)d_in[3];
    const float* Wo = (const float*)d_in[4];
    float* out = (float*)d_out;

    float *qp, *kp, *vp, *ap;
    cudaGetSymbolAddress((void**)&qp, g_q);
    cudaGetSymbolAddress((void**)&kp, g_k);
    cudaGetSymbolAddress((void**)&vp, g_v);
    cudaGetSymbolAddress((void**)&ap, g_attn);

    const int attn_smem = (QT*HD + 128*KSTRIDE + QT*PST + 3*QT) * (int)sizeof(float);
    cudaFuncSetAttribute(attn_kernel, cudaFuncAttributeMaxDynamicSharedMemorySize,
                         attn_smem);

    dim3 gq(EMB / 128, MROWS / 128);     // (16, 32)
    dim3 gkv(KVDIM / 128, MROWS / 128);  // (4, 32)
    dim3 ga(S_LEN / QT, NH, BATCH);      // (32, 16, 2)

    sgemm_nt<<<gq, 256>>>(x, Wq, qp, MROWS, EMB, EMB);
    sgemm_nt<<<gkv, 256>>>(x, Wk, kp, MROWS, KVDIM, EMB);
    sgemm_nt<<<gkv, 256>>>(x, Wv, vp, MROWS, KVDIM, EMB);
    attn_kernel<<<ga, 256, attn_smem>>>();
    sgemm_nt<<<gq, 256>>>(ap, Wo, out, MROWS, EMB, EMB);
}

// round 4
// speedup vs baseline: 1.7654x; 1.7654x over previous
#include <cuda_runtime.h>
#include <cuda_bf16.h>
#include <cstdint>
#include <math.h>

#define S_LEN 2048
#define BATCH 2
#define EMB   2048
#define NH    16
#define NKV   4
#define HD    128
#define KVDIM (NKV*HD)        // 512
#define MROWS (BATCH*S_LEN)   // 4096
#define K2    (3*EMB)         // 6144: A=[hi|lo|hi], B=[hi|hi|lo]

#define QT 64
#define KT 64
#define KSTRIDE 68
#define PST 65

// ---------------- scratch (allocation-free) ----------------
__device__ float g_q[(size_t)MROWS * EMB];
__device__ float g_k[(size_t)MROWS * KVDIM];
__device__ float g_v[(size_t)MROWS * KVDIM];
__device__ float g_attn[(size_t)MROWS * EMB];

__device__ __nv_bfloat16 g_x2[(size_t)MROWS * K2];
__device__ __nv_bfloat16 g_a2[(size_t)MROWS * K2];
__device__ __nv_bfloat16 g_wq2[(size_t)EMB * K2];
__device__ __nv_bfloat16 g_wo2[(size_t)EMB * K2];
__device__ __nv_bfloat16 g_wk2[(size_t)KVDIM * K2];
__device__ __nv_bfloat16 g_wv2[(size_t)KVDIM * K2];

// ----------------------------------------------------------------------------
// split: fp32 [M,K] -> bf16 [M,3K].
// mode 0 (A side / activations):  [hi | lo | hi]
// mode 1 (B side / weights):      [hi | hi | lo]
// Products per K-segment: hi*hi + lo*hi + hi*lo  (lo*lo dropped, ~2^-18 rel)
// ----------------------------------------------------------------------------
__global__ __launch_bounds__(256) void split_hl(const float* __restrict__ in,
                                                __nv_bfloat16* __restrict__ out,
                                                int K, int total4, int mode)
{
    int i = blockIdx.x * blockDim.x + threadIdx.x;
    if (i >= total4) return;
    int per_row = K >> 2;
    int row = i / per_row;
    int c4 = (i - row * per_row) * 4;
    float4 v = *(const float4*)(in + (size_t)row * K + c4);
    float f[4] = {v.x, v.y, v.z, v.w};
    __nv_bfloat16 hi[4], lo[4];
    #pragma unroll
    for (int j = 0; j < 4; j++) {
        hi[j] = __float2bfloat16(f[j]);
        lo[j] = __float2bfloat16(f[j] - __bfloat162float(hi[j]));
    }
    __nv_bfloat16* o = out + (size_t)row * (3 * K);
    __nv_bfloat162 h01, h23, l01, l23;
    h01.x = hi[0]; h01.y = hi[1]; h23.x = hi[2]; h23.y = hi[3];
    l01.x = lo[0]; l01.y = lo[1]; l23.x = lo[2]; l23.y = lo[3];
    // segment 0: hi (both modes)
    *(__nv_bfloat162*)(o + c4)     = h01;
    *(__nv_bfloat162*)(o + c4 + 2) = h23;
    if (mode == 0) {
        // A: [hi | lo | hi]
        *(__nv_bfloat162*)(o + K + c4)         = l01;
        *(__nv_bfloat162*)(o + K + c4 + 2)     = l23;
        *(__nv_bfloat162*)(o + 2*K + c4)       = h01;
        *(__nv_bfloat162*)(o + 2*K + c4 + 2)   = h23;
    } else {
        // B: [hi | hi | lo]
        *(__nv_bfloat162*)(o + K + c4)         = h01;
        *(__nv_bfloat162*)(o + K + c4 + 2)     = h23;
        *(__nv_bfloat162*)(o + 2*K + c4)       = l01;
        *(__nv_bfloat162*)(o + 2*K + c4 + 2)   = l23;
    }
}

// ----------------------------------------------------------------------------
// HMMA GEMM: C[M,N] = A[M,K] @ B[N,K]^T, bf16 in, fp32 accumulate.
// mma.sync.m16n8k16 (sm_80 baseline PTX). CTA 128x128, BK=64, SW128 swizzle,
// 3-stage cp.async pipeline, 8 warps 4(m) x 2(n), warp tile 32x64.
// ----------------------------------------------------------------------------
#define GSTAGE_BYTES 32768          // 16KB A + 16KB B per stage
#define GEMM_SMEM (3 * GSTAGE_BYTES)

__device__ __forceinline__ void ldsm_x4(uint32_t* r, uint32_t addr) {
    asm volatile("ldmatrix.sync.aligned.m8n8.x4.shared.b16 {%0,%1,%2,%3}, [%4];"
                 : "=r"(r[0]), "=r"(r[1]), "=r"(r[2]), "=r"(r[3]) : "r"(addr));
}
__device__ __forceinline__ void mma_16816(float* d, const uint32_t* a, uint32_t b0,
                                          uint32_t b1) {
    asm volatile(
        "mma.sync.aligned.m16n8k16.row.col.f32.bf16.bf16.f32 "
        "{%0,%1,%2,%3}, {%4,%5,%6,%7}, {%8,%9}, {%0,%1,%2,%3};"
        : "+f"(d[0]), "+f"(d[1]), "+f"(d[2]), "+f"(d[3])
        : "r"(a[0]), "r"(a[1]), "r"(a[2]), "r"(a[3]), "r"(b0), "r"(b1));
}

__global__ __launch_bounds__(256) void gemm_mma(const __nv_bfloat16* __restrict__ A,
                                                const __nv_bfloat16* __restrict__ B,
                                                float* __restrict__ C,
                                                int M, int N, int K)
{
    extern __shared__ __align__(1024) char smem[];
    const uint32_t sbase = (uint32_t)__cvta_generic_to_shared(smem);

    const int tid  = threadIdx.x;
    const int warp = tid >> 5, lane = tid & 31;
    const int wm   = warp & 3, wn = warp >> 2;      // 4 x 2 warp grid
    const int brow = blockIdx.y * 128, bcol = blockIdx.x * 128;

    uint32_t dstA[4], dstB[4];
    const __nv_bfloat16* srcA[4];
    const __nv_bfloat16* srcB[4];
    #pragma unroll
    for (int it = 0; it < 4; it++) {
        int id  = it * 256 + tid;
        int row = id >> 3, c = id & 7;
        uint32_t sw = row * 128 + ((c ^ (row & 7)) * 16);
        dstA[it] = sbase + sw;
        dstB[it] = sbase + 16384 + sw;
        srcA[it] = A + (size_t)(brow + row) * K + c * 8;
        srcB[it] = B + (size_t)(bcol + row) * K + c * 8;
    }

    const int NT = K / 64;

    #define LOAD_STAGE(s, kt) do {                                             \
        uint32_t so = (uint32_t)(s) * GSTAGE_BYTES;                            \
        int ko = (kt) * 64;                                                    \
        _Pragma("unroll")                                                      \
        for (int it = 0; it < 4; it++) {                                       \
            asm volatile("cp.async.cg.shared.global [%0], [%1], 16;"           \
                         :: "r"(dstA[it] + so), "l"(srcA[it] + ko));           \
            asm volatile("cp.async.cg.shared.global [%0], [%1], 16;"           \
                         :: "r"(dstB[it] + so), "l"(srcB[it] + ko));           \
        }                                                                      \
        asm volatile("cp.async.commit_group;");                                \
    } while (0)

    LOAD_STAGE(0, 0);
    LOAD_STAGE(1, 1);
    LOAD_STAGE(2, 2);

    float acc[2][8][4];
    #pragma unroll
    for (int i = 0; i < 2; i++)
        #pragma unroll
        for (int j = 0; j < 8; j++)
            #pragma unroll
            for (int q = 0; q < 4; q++) acc[i][j][q] = 0.f;

    const int frow = lane & 15;
    const int fhi  = lane >> 4;

    for (int kt = 0; kt < NT; kt++) {
        int s = kt % 3;
        asm volatile("cp.async.wait_group 2;" ::: "memory");
        __syncthreads();

        uint32_t abase = sbase + s * GSTAGE_BYTES;
        uint32_t bbase = abase + 16384;

        #pragma unroll
        for (int ks = 0; ks < 4; ks++) {
            int c = ks * 2 + fhi;
            uint32_t a[2][4], bb[4][4];
            #pragma unroll
            for (int i = 0; i < 2; i++) {
                int row = wm * 32 + i * 16 + frow;
                ldsm_x4(a[i], abase + row * 128 + ((c ^ (row & 7)) * 16));
            }
            #pragma unroll
            for (int g = 0; g < 4; g++) {
                int row = wn * 64 + g * 16 + frow;
                ldsm_x4(bb[g], bbase + row * 128 + ((c ^ (row & 7)) * 16));
            }
            #pragma unroll
            for (int i = 0; i < 2; i++)
                #pragma unroll
                for (int j = 0; j < 8; j++) {
                    int g = j >> 1;
                    if (j & 1) mma_16816(acc[i][j], a[i], bb[g][1], bb[g][3]);
                    else       mma_16816(acc[i][j], a[i], bb[g][0], bb[g][2]);
                }
        }
        __syncthreads();
        if (kt + 3 < NT) { LOAD_STAGE(s, kt + 3); }
        else { asm volatile("cp.async.commit_group;"); }
    }

    const int erow = lane >> 2;
    const int ecol = (lane & 3) * 2;
    #pragma unroll
    for (int i = 0; i < 2; i++) {
        int r0 = brow + wm * 32 + i * 16 + erow;
        #pragma unroll
        for (int j = 0; j < 8; j++) {
            int cc = bcol + wn * 64 + j * 8 + ecol;
            float2 v0 = make_float2(acc[i][j][0], acc[i][j][1]);
            float2 v1 = make_float2(acc[i][j][2], acc[i][j][3]);
            *(float2*)(C + (size_t)r0 * N + cc)       = v0;
            *(float2*)(C + (size_t)(r0 + 8) * N + cc) = v1;
        }
    }
    #undef LOAD_STAGE
}

// ----------------------------------------------------------------------------
// Flash attention (unchanged): causal, GQA, fp32.
// ----------------------------------------------------------------------------
__global__ __launch_bounds__(256) void attn_kernel()
{
    extern __shared__ float sm[];
    float* Qs     = sm;
    float* KV     = Qs + QT * HD;
    float* Ps     = KV + 128 * KSTRIDE;
    float* row_m  = Ps + QT * PST;
    float* row_l  = row_m + QT;
    float* row_cf = row_l + QT;

    const int tid = threadIdx.x;
    const int iq  = blockIdx.x;
    const int h   = blockIdx.y;
    const int b   = blockIdx.z;
    const int kvh = h / (NH / NKV);
    const int tx  = tid & 15;
    const int ty  = tid >> 4;

    {
        const float scale = 0.08838834764831845f;
        const float* qg = g_q + ((size_t)(b * S_LEN + iq * QT)) * EMB + h * HD;
        #pragma unroll
        for (int it = 0; it < 8; it++) {
            int idx = it * 256 + tid;
            int r   = idx >> 5;
            int c4  = (idx & 31) * 4;
            float4 v = *(const float4*)(qg + (size_t)r * EMB + c4);
            float* dst = Qs + r * HD + c4;
            dst[0] = v.x * scale; dst[1] = v.y * scale;
            dst[2] = v.z * scale; dst[3] = v.w * scale;
        }
    }
    if (tid < QT) { row_m[tid] = -3.0e38f; row_l[tid] = 0.f; }

    float o[4][8];
    #pragma unroll
    for (int i = 0; i < 4; i++)
        #pragma unroll
        for (int j = 0; j < 8; j++) o[i][j] = 0.f;

    const float* kg_base = g_k + ((size_t)(b * S_LEN)) * KVDIM + kvh * HD;
    const float* vg_base = g_v + ((size_t)(b * S_LEN)) * KVDIM + kvh * HD;

    for (int jt = 0; jt <= iq; jt++) {
        __syncthreads();
        {
            const float* kg = kg_base + (size_t)(jt * KT) * KVDIM;
            int t  = tid & 63;
            int dq = tid >> 6;
            #pragma unroll
            for (int rep = 0; rep < 8; rep++) {
                int d0 = (rep * 4 + dq) * 4;
                float4 k4 = *(const float4*)(kg + (size_t)t * KVDIM + d0);
                KV[(d0+0)*KSTRIDE + t] = k4.x;
                KV[(d0+1)*KSTRIDE + t] = k4.y;
                KV[(d0+2)*KSTRIDE + t] = k4.z;
                KV[(d0+3)*KSTRIDE + t] = k4.w;
            }
        }
        __syncthreads();

        float sc[4][4];
        #pragma unroll
        for (int i = 0; i < 4; i++)
            #pragma unroll
            for (int j = 0; j < 4; j++) sc[i][j] = 0.f;
        {
            const float* q0 = Qs + (ty*4 + 0) * HD;
            const float* q1 = Qs + (ty*4 + 1) * HD;
            const float* q2 = Qs + (ty*4 + 2) * HD;
            const float* q3 = Qs + (ty*4 + 3) * HD;
            for (int d0 = 0; d0 < HD; d0 += 4) {
                float4 a4 = *(const float4*)(q0 + d0);
                float4 b4 = *(const float4*)(q1 + d0);
                float4 c4 = *(const float4*)(q2 + d0);
                float4 e4 = *(const float4*)(q3 + d0);
                float qA[4] = {a4.x, a4.y, a4.z, a4.w};
                float qB[4] = {b4.x, b4.y, b4.z, b4.w};
                float qC[4] = {c4.x, c4.y, c4.z, c4.w};
                float qD[4] = {e4.x, e4.y, e4.z, e4.w};
                #pragma unroll
                for (int dd = 0; dd < 4; dd++) {
                    float4 k4 = *(const float4*)(KV + (d0 + dd) * KSTRIDE + tx * 4);
                    sc[0][0] += qA[dd]*k4.x; sc[0][1] += qA[dd]*k4.y;
                    sc[0][2] += qA[dd]*k4.z; sc[0][3] += qA[dd]*k4.w;
                    sc[1][0] += qB[dd]*k4.x; sc[1][1] += qB[dd]*k4.y;
                    sc[1][2] += qB[dd]*k4.z; sc[1][3] += qB[dd]*k4.w;
                    sc[2][0] += qC[dd]*k4.x; sc[2][1] += qC[dd]*k4.y;
                    sc[2][2] += qC[dd]*k4.z; sc[2][3] += qC[dd]*k4.w;
                    sc[3][0] += qD[dd]*k4.x; sc[3][1] += qD[dd]*k4.y;
                    sc[3][2] += qD[dd]*k4.z; sc[3][3] += qD[dd]*k4.w;
                }
            }
        }

        #pragma unroll
        for (int i = 0; i < 4; i++) {
            int r = ty * 4 + i;
            int sglob = iq * QT + r;
            #pragma unroll
            for (int j = 0; j < 4; j++) {
                int c = tx * 4 + j;
                float val = sc[i][j];
                if (jt * KT + c > sglob) val = -3.0e38f;
                Ps[r * PST + c] = val;
            }
        }
        __syncthreads();

        if (tid < QT) {
            int r = tid;
            float m_old = row_m[r];
            float mx = m_old;
            for (int c = 0; c < KT; c++) mx = fmaxf(mx, Ps[r * PST + c]);
            float cf = __expf(m_old - mx);
            float l = row_l[r] * cf;
            for (int c = 0; c < KT; c++) {
                float p = __expf(Ps[r * PST + c] - mx);
                Ps[r * PST + c] = p;
                l += p;
            }
            row_m[r] = mx; row_l[r] = l; row_cf[r] = cf;
        }
        __syncthreads();

        {
            const float* vg = vg_base + (size_t)(jt * KT) * KVDIM;
            #pragma unroll
            for (int it = 0; it < 8; it++) {
                int idx = it * 256 + tid;
                int r   = idx >> 5;
                int c4  = (idx & 31) * 4;
                *(float4*)(KV + r * HD + c4) =
                    *(const float4*)(vg + (size_t)r * KVDIM + c4);
            }
        }
        __syncthreads();

        float cfr[4];
        #pragma unroll
        for (int i = 0; i < 4; i++) cfr[i] = row_cf[ty * 4 + i];
        #pragma unroll
        for (int i = 0; i < 4; i++)
            #pragma unroll
            for (int j = 0; j < 8; j++) o[i][j] *= cfr[i];

        for (int t = 0; t < KT; t++) {
            float p0 = Ps[(ty*4 + 0) * PST + t];
            float p1 = Ps[(ty*4 + 1) * PST + t];
            float p2 = Ps[(ty*4 + 2) * PST + t];
            float p3 = Ps[(ty*4 + 3) * PST + t];
            float4 va = *(const float4*)(KV + t * HD + tx * 8);
            float4 vb = *(const float4*)(KV + t * HD + tx * 8 + 4);
            o[0][0]+=p0*va.x; o[0][1]+=p0*va.y; o[0][2]+=p0*va.z; o[0][3]+=p0*va.w;
            o[0][4]+=p0*vb.x; o[0][5]+=p0*vb.y; o[0][6]+=p0*vb.z; o[0][7]+=p0*vb.w;
            o[1][0]+=p1*va.x; o[1][1]+=p1*va.y; o[1][2]+=p1*va.z; o[1][3]+=p1*va.w;
            o[1][4]+=p1*vb.x; o[1][5]+=p1*vb.y; o[1][6]+=p1*vb.z; o[1][7]+=p1*vb.w;
            o[2][0]+=p2*va.x; o[2][1]+=p2*va.y; o[2][2]+=p2*va.z; o[2][3]+=p2*va.w;
            o[2][4]+=p2*vb.x; o[2][5]+=p2*vb.y; o[2][6]+=p2*vb.z; o[2][7]+=p2*vb.w;
            o[3][0]+=p3*va.x; o[3][1]+=p3*va.y; o[3][2]+=p3*va.z; o[3][3]+=p3*va.w;
            o[3][4]+=p3*vb.x; o[3][5]+=p3*vb.y; o[3][6]+=p3*vb.z; o[3][7]+=p3*vb.w;
        }
    }

    float invl[4];
    #pragma unroll
    for (int i = 0; i < 4; i++) invl[i] = 1.f / row_l[ty * 4 + i];
    float* og = g_attn + ((size_t)(b * S_LEN + iq * QT)) * EMB + h * HD;
    #pragma unroll
    for (int i = 0; i < 4; i++) {
        float* orow = og + (size_t)(ty * 4 + i) * EMB + tx * 8;
        float4 r0, r1;
        r0.x = o[i][0]*invl[i]; r0.y = o[i][1]*invl[i];
        r0.z = o[i][2]*invl[i]; r0.w = o[i][3]*invl[i];
        r1.x = o[i][4]*invl[i]; r1.y = o[i][5]*invl[i];
        r1.z = o[i][6]*invl[i]; r1.w = o[i][7]*invl[i];
        *(float4*)(orow + 0) = r0;
        *(float4*)(orow + 4) = r1;
    }
}

// ----------------------------------------------------------------------------
// Launch
// ----------------------------------------------------------------------------
extern "C" void kernel_launch(void* const* d_in, const int* in_sizes, int n_in,
                              void* d_out, int out_size)
{
    const float* x  = (const float*)d_in[0];
    const float* Wq = (const float*)d_in[1];
    const float* Wk = (const float*)d_in[2];
    const float* Wv = (const float*)d_in[3];
    const float* Wo = (const float*)d_in[4];
    float* out = (float*)d_out;

    float *qp, *kp, *vp, *ap;
    __nv_bfloat16 *x2, *a2, *wq2, *wk2, *wv2, *wo2;
    cudaGetSymbolAddress((void**)&qp, g_q);
    cudaGetSymbolAddress((void**)&kp, g_k);
    cudaGetSymbolAddress((void**)&vp, g_v);
    cudaGetSymbolAddress((void**)&ap, g_attn);
    cudaGetSymbolAddress((void**)&x2, g_x2);
    cudaGetSymbolAddress((void**)&a2, g_a2);
    cudaGetSymbolAddress((void**)&wq2, g_wq2);
    cudaGetSymbolAddress((void**)&wk2, g_wk2);
    cudaGetSymbolAddress((void**)&wv2, g_wv2);
    cudaGetSymbolAddress((void**)&wo2, g_wo2);

    const int attn_smem = (QT*HD + 128*KSTRIDE + QT*PST + 3*QT) * (int)sizeof(float);
    cudaFuncSetAttribute(attn_kernel, cudaFuncAttributeMaxDynamicSharedMemorySize, attn_smem);
    cudaFuncSetAttribute(gemm_mma, cudaFuncAttributeMaxDynamicSharedMemorySize, GEMM_SMEM);

    // split conversions: mode 0 = A side [hi|lo|hi], mode 1 = B side [hi|hi|lo]
    {
        int t4 = MROWS * EMB / 4;
        split_hl<<<(t4 + 255) / 256, 256>>>(x, x2, EMB, t4, 0);
        t4 = EMB * EMB / 4;
        split_hl<<<(t4 + 255) / 256, 256>>>(Wq, wq2, EMB, t4, 1);
        split_hl<<<(t4 + 255) / 256, 256>>>(Wo, wo2, EMB, t4, 1);
        t4 = KVDIM * EMB / 4;
        split_hl<<<(t4 + 255) / 256, 256>>>(Wk, wk2, EMB, t4, 1);
        split_hl<<<(t4 + 255) / 256, 256>>>(Wv, wv2, EMB, t4, 1);
    }

    dim3 gq(EMB / 128, MROWS / 128);     // (16, 32)
    dim3 gkv(KVDIM / 128, MROWS / 128);  // (4, 32)
    dim3 ga(S_LEN / QT, NH, BATCH);      // (32, 16, 2)

    gemm_mma<<<gq,  256, GEMM_SMEM>>>(x2, wq2, qp, MROWS, EMB,   K2);
    gemm_mma<<<gkv, 256, GEMM_SMEM>>>(x2, wk2, kp, MROWS, KVDIM, K2);
    gemm_mma<<<gkv, 256, GEMM_SMEM>>>(x2, wv2, vp, MROWS, KVDIM, K2);

    attn_kernel<<<ga, 256, attn_smem>>>();

    {
        int t4 = MROWS * EMB / 4;
        split_hl<<<(t4 + 255) / 256, 256>>>(ap, a2, EMB, t4, 0);
    }
    gemm_mma<<<gq, 256, GEMM_SMEM>>>(a2, wo2, out, MROWS, EMB, K2);
}

// round 6
// speedup vs baseline: 3.1823x; 1.8026x over previous
#include <cuda_runtime.h>
#include <cuda_bf16.h>
#include <cstdint>
#include <math.h>

#define S_LEN 2048
#define BATCH 2
#define EMB   2048
#define NH    16
#define NKV   4
#define HD    128
#define KVDIM (NKV*HD)        // 512
#define MROWS (BATCH*S_LEN)   // 4096
#define K2    (3*EMB)         // 6144: A=[hi|lo|hi], B=[hi|hi|lo]

// ---------------- scratch (allocation-free) ----------------
__device__ float g_q[(size_t)MROWS * EMB];
__device__ float g_k[(size_t)MROWS * KVDIM];
__device__ float g_v[(size_t)MROWS * KVDIM];
__device__ float g_attn[(size_t)MROWS * EMB];

__device__ __nv_bfloat16 g_x2[(size_t)MROWS * K2];
__device__ __nv_bfloat16 g_a2[(size_t)MROWS * K2];
__device__ __nv_bfloat16 g_wq2[(size_t)EMB * K2];
__device__ __nv_bfloat16 g_wo2[(size_t)EMB * K2];
__device__ __nv_bfloat16 g_wk2[(size_t)KVDIM * K2];
__device__ __nv_bfloat16 g_wv2[(size_t)KVDIM * K2];

// attention bf16 operands (hi/lo pairs)
__device__ __nv_bfloat16 g_qh[(size_t)MROWS * EMB];
__device__ __nv_bfloat16 g_ql[(size_t)MROWS * EMB];
__device__ __nv_bfloat16 g_kh[(size_t)MROWS * KVDIM];
__device__ __nv_bfloat16 g_kl[(size_t)MROWS * KVDIM];
__device__ __nv_bfloat16 g_vh[(size_t)MROWS * KVDIM];
__device__ __nv_bfloat16 g_vl[(size_t)MROWS * KVDIM];

// ---------------- common MMA helpers ----------------
__device__ __forceinline__ void ldsm_x4(uint32_t* r, uint32_t addr) {
    asm volatile("ldmatrix.sync.aligned.m8n8.x4.shared.b16 {%0,%1,%2,%3}, [%4];"
                 : "=r"(r[0]), "=r"(r[1]), "=r"(r[2]), "=r"(r[3]) : "r"(addr));
}
__device__ __forceinline__ void ldsm_x4_t(uint32_t* r, uint32_t addr) {
    asm volatile("ldmatrix.sync.aligned.m8n8.x4.trans.shared.b16 {%0,%1,%2,%3}, [%4];"
                 : "=r"(r[0]), "=r"(r[1]), "=r"(r[2]), "=r"(r[3]) : "r"(addr));
}
__device__ __forceinline__ void mma_16816(float* d, const uint32_t* a, uint32_t b0,
                                          uint32_t b1) {
    asm volatile(
        "mma.sync.aligned.m16n8k16.row.col.f32.bf16.bf16.f32 "
        "{%0,%1,%2,%3}, {%4,%5,%6,%7}, {%8,%9}, {%0,%1,%2,%3};"
        : "+f"(d[0]), "+f"(d[1]), "+f"(d[2]), "+f"(d[3])
        : "r"(a[0]), "r"(a[1]), "r"(a[2]), "r"(a[3]), "r"(b0), "r"(b1));
}
#define CPA16(dst, src) \
    asm volatile("cp.async.cg.shared.global [%0], [%1], 16;" :: "r"(dst), "l"(src))

// ----------------------------------------------------------------------------
// split: fp32 [M,K] -> bf16 [M,3K] (GEMM operands)
// ----------------------------------------------------------------------------
__global__ __launch_bounds__(256) void split_hl(const float* __restrict__ in,
                                                __nv_bfloat16* __restrict__ out,
                                                int K, int total4, int mode)
{
    int i = blockIdx.x * blockDim.x + threadIdx.x;
    if (i >= total4) return;
    int per_row = K >> 2;
    int row = i / per_row;
    int c4 = (i - row * per_row) * 4;
    float4 v = *(const float4*)(in + (size_t)row * K + c4);
    float f[4] = {v.x, v.y, v.z, v.w};
    __nv_bfloat16 hi[4], lo[4];
    #pragma unroll
    for (int j = 0; j < 4; j++) {
        hi[j] = __float2bfloat16(f[j]);
        lo[j] = __float2bfloat16(f[j] - __bfloat162float(hi[j]));
    }
    __nv_bfloat16* o = out + (size_t)row * (3 * K);
    __nv_bfloat162 h01, h23, l01, l23;
    h01.x = hi[0]; h01.y = hi[1]; h23.x = hi[2]; h23.y = hi[3];
    l01.x = lo[0]; l01.y = lo[1]; l23.x = lo[2]; l23.y = lo[3];
    *(__nv_bfloat162*)(o + c4)     = h01;
    *(__nv_bfloat162*)(o + c4 + 2) = h23;
    if (mode == 0) {
        *(__nv_bfloat162*)(o + K + c4)         = l01;
        *(__nv_bfloat162*)(o + K + c4 + 2)     = l23;
        *(__nv_bfloat162*)(o + 2*K + c4)       = h01;
        *(__nv_bfloat162*)(o + 2*K + c4 + 2)   = h23;
    } else {
        *(__nv_bfloat162*)(o + K + c4)         = h01;
        *(__nv_bfloat162*)(o + K + c4 + 2)     = h23;
        *(__nv_bfloat162*)(o + 2*K + c4)       = l01;
        *(__nv_bfloat162*)(o + 2*K + c4 + 2)   = l23;
    }
}

// flat split: fp32 -> hi bf16 + lo bf16 (scaled)
__global__ __launch_bounds__(256) void split2(const float* __restrict__ in,
                                              __nv_bfloat16* __restrict__ hi,
                                              __nv_bfloat16* __restrict__ lo,
                                              float scale, int total4)
{
    int i = blockIdx.x * blockDim.x + threadIdx.x;
    if (i >= total4) return;
    float4 v = *(const float4*)(in + (size_t)i * 4);
    float f[4] = {v.x * scale, v.y * scale, v.z * scale, v.w * scale};
    __nv_bfloat162 h01, h23, l01, l23;
    __nv_bfloat16 h[4];
    #pragma unroll
    for (int j = 0; j < 4; j++) h[j] = __float2bfloat16(f[j]);
    h01.x = h[0]; h01.y = h[1]; h23.x = h[2]; h23.y = h[3];
    l01.x = __float2bfloat16(f[0] - __bfloat162float(h[0]));
    l01.y = __float2bfloat16(f[1] - __bfloat162float(h[1]));
    l23.x = __float2bfloat16(f[2] - __bfloat162float(h[2]));
    l23.y = __float2bfloat16(f[3] - __bfloat162float(h[3]));
    *(__nv_bfloat162*)(hi + (size_t)i * 4)     = h01;
    *(__nv_bfloat162*)(hi + (size_t)i * 4 + 2) = h23;
    *(__nv_bfloat162*)(lo + (size_t)i * 4)     = l01;
    *(__nv_bfloat162*)(lo + (size_t)i * 4 + 2) = l23;
}

// ----------------------------------------------------------------------------
// HMMA GEMM (unchanged, passing)
// ----------------------------------------------------------------------------
#define GSTAGE_BYTES 32768
#define GEMM_SMEM (3 * GSTAGE_BYTES)

__global__ __launch_bounds__(256) void gemm_mma(const __nv_bfloat16* __restrict__ A,
                                                const __nv_bfloat16* __restrict__ B,
                                                float* __restrict__ C,
                                                int M, int N, int K)
{
    extern __shared__ __align__(1024) char smem[];
    const uint32_t sbase = (uint32_t)__cvta_generic_to_shared(smem);

    const int tid  = threadIdx.x;
    const int warp = tid >> 5, lane = tid & 31;
    const int wm   = warp & 3, wn = warp >> 2;
    const int brow = blockIdx.y * 128, bcol = blockIdx.x * 128;

    uint32_t dstA[4], dstB[4];
    const __nv_bfloat16* srcA[4];
    const __nv_bfloat16* srcB[4];
    #pragma unroll
    for (int it = 0; it < 4; it++) {
        int id  = it * 256 + tid;
        int row = id >> 3, c = id & 7;
        uint32_t sw = row * 128 + ((c ^ (row & 7)) * 16);
        dstA[it] = sbase + sw;
        dstB[it] = sbase + 16384 + sw;
        srcA[it] = A + (size_t)(brow + row) * K + c * 8;
        srcB[it] = B + (size_t)(bcol + row) * K + c * 8;
    }

    const int NT = K / 64;

    #define LOAD_STAGE(s, kt) do {                                             \
        uint32_t so = (uint32_t)(s) * GSTAGE_BYTES;                            \
        int ko = (kt) * 64;                                                    \
        _Pragma("unroll")                                                      \
        for (int it = 0; it < 4; it++) {                                       \
            CPA16(dstA[it] + so, srcA[it] + ko);                               \
            CPA16(dstB[it] + so, srcB[it] + ko);                               \
        }                                                                      \
        asm volatile("cp.async.commit_group;");                                \
    } while (0)

    LOAD_STAGE(0, 0);
    LOAD_STAGE(1, 1);
    LOAD_STAGE(2, 2);

    float acc[2][8][4];
    #pragma unroll
    for (int i = 0; i < 2; i++)
        #pragma unroll
        for (int j = 0; j < 8; j++)
            #pragma unroll
            for (int q = 0; q < 4; q++) acc[i][j][q] = 0.f;

    const int frow = lane & 15;
    const int fhi  = lane >> 4;

    for (int kt = 0; kt < NT; kt++) {
        int s = kt % 3;
        asm volatile("cp.async.wait_group 2;" ::: "memory");
        __syncthreads();

        uint32_t abase = sbase + s * GSTAGE_BYTES;
        uint32_t bbase = abase + 16384;

        #pragma unroll
        for (int ks = 0; ks < 4; ks++) {
            int c = ks * 2 + fhi;
            uint32_t a[2][4], bb[4][4];
            #pragma unroll
            for (int i = 0; i < 2; i++) {
                int row = wm * 32 + i * 16 + frow;
                ldsm_x4(a[i], abase + row * 128 + ((c ^ (row & 7)) * 16));
            }
            #pragma unroll
            for (int g = 0; g < 4; g++) {
                int row = wn * 64 + g * 16 + frow;
                ldsm_x4(bb[g], bbase + row * 128 + ((c ^ (row & 7)) * 16));
            }
            #pragma unroll
            for (int i = 0; i < 2; i++)
                #pragma unroll
                for (int j = 0; j < 8; j++) {
                    int g = j >> 1;
                    if (j & 1) mma_16816(acc[i][j], a[i], bb[g][1], bb[g][3]);
                    else       mma_16816(acc[i][j], a[i], bb[g][0], bb[g][2]);
                }
        }
        __syncthreads();
        if (kt + 3 < NT) { LOAD_STAGE(s, kt + 3); }
        else { asm volatile("cp.async.commit_group;"); }
    }

    const int erow = lane >> 2;
    const int ecol = (lane & 3) * 2;
    #pragma unroll
    for (int i = 0; i < 2; i++) {
        int r0 = brow + wm * 32 + i * 16 + erow;
        #pragma unroll
        for (int j = 0; j < 8; j++) {
            int cc = bcol + wn * 64 + j * 8 + ecol;
            float2 v0 = make_float2(acc[i][j][0], acc[i][j][1]);
            float2 v1 = make_float2(acc[i][j][2], acc[i][j][3]);
            *(float2*)(C + (size_t)r0 * N + cc)       = v0;
            *(float2*)(C + (size_t)(r0 + 8) * N + cc) = v1;
        }
    }
    #undef LOAD_STAGE
}

// ----------------------------------------------------------------------------
// HMMA flash attention: causal, GQA. Full hi/lo split on QK AND PV.
// ----------------------------------------------------------------------------
#define AQH 0
#define AQL 16384
#define AKH 32768
#define AKL 49152
#define AVH 65536
#define AVL 81920
#define APS 98304                      // fp32 scores 64 x 68 = 17408 B
#define APB (APS + 64*68*4)            // bf16 P hi 64 x 64 = 8192 B
#define APL (APB + 8192)               // bf16 P lo
#define AST (APL + 8192)               // row_m, row_l, row_cf
#define ATT_SMEM (AST + 64*4*3)        // ~129.8 KB -> 1 CTA/SM

__device__ __forceinline__ uint32_t sw256(int r, int c) {  // c: 16B chunk 0..15
    return (uint32_t)(r * 256 + (((c & 7) ^ (r & 7)) | (c & 8)) * 16);
}
__device__ __forceinline__ uint32_t sw128(int r, int c) {  // c: 16B chunk 0..7
    return (uint32_t)(r * 128 + ((c ^ (r & 7)) * 16));
}

__global__ __launch_bounds__(256, 1) void attn_mma()
{
    extern __shared__ __align__(1024) char smraw[];
    const uint32_t sb = (uint32_t)__cvta_generic_to_shared(smraw);
    float* Ps     = (float*)(smraw + APS);
    float* row_m  = (float*)(smraw + AST);
    float* row_l  = row_m + 64;
    float* row_cf = row_l + 64;

    const int tid  = threadIdx.x;
    const int warp = tid >> 5, lane = tid & 31;
    const int wm   = warp & 3, wn = warp >> 2;
    const int frow = lane & 15, fhi = lane >> 4;
    const int iq   = blockIdx.x;
    const int h    = blockIdx.y;
    const int b    = blockIdx.z;
    const int kvh  = h / (NH / NKV);

    // ---- load Q hi/lo tiles ----
    {
        const __nv_bfloat16* qh = g_qh + ((size_t)(b * S_LEN + iq * 64)) * EMB + h * HD;
        const __nv_bfloat16* ql = g_ql + ((size_t)(b * S_LEN + iq * 64)) * EMB + h * HD;
        #pragma unroll
        for (int it = 0; it < 4; it++) {
            int id = it * 256 + tid;
            int r = id >> 4, c = id & 15;
            CPA16(sb + AQH + sw256(r, c), qh + (size_t)r * EMB + c * 8);
            CPA16(sb + AQL + sw256(r, c), ql + (size_t)r * EMB + c * 8);
        }
        asm volatile("cp.async.commit_group;");
    }
    if (tid < 64) { row_m[tid] = -3.0e38f; row_l[tid] = 0.f; }

    float o[8][4];
    #pragma unroll
    for (int j = 0; j < 8; j++)
        #pragma unroll
        for (int q = 0; q < 4; q++) o[j][q] = 0.f;

    asm volatile("cp.async.wait_group 0;" ::: "memory");
    __syncthreads();

    const __nv_bfloat16* khb = g_kh + ((size_t)(b * S_LEN)) * KVDIM + kvh * HD;
    const __nv_bfloat16* klb = g_kl + ((size_t)(b * S_LEN)) * KVDIM + kvh * HD;
    const __nv_bfloat16* vhb = g_vh + ((size_t)(b * S_LEN)) * KVDIM + kvh * HD;
    const __nv_bfloat16* vlb = g_vl + ((size_t)(b * S_LEN)) * KVDIM + kvh * HD;

    for (int jt = 0; jt <= iq; jt++) {
        // ---- load K hi/lo + V hi/lo tiles ----
        {
            const __nv_bfloat16* kh = khb + (size_t)(jt * 64) * KVDIM;
            const __nv_bfloat16* kl = klb + (size_t)(jt * 64) * KVDIM;
            const __nv_bfloat16* vh = vhb + (size_t)(jt * 64) * KVDIM;
            const __nv_bfloat16* vl = vlb + (size_t)(jt * 64) * KVDIM;
            #pragma unroll
            for (int it = 0; it < 4; it++) {
                int id = it * 256 + tid;
                int r = id >> 4, c = id & 15;
                CPA16(sb + AKH + sw256(r, c), kh + (size_t)r * KVDIM + c * 8);
                CPA16(sb + AKL + sw256(r, c), kl + (size_t)r * KVDIM + c * 8);
                CPA16(sb + AVH + sw256(r, c), vh + (size_t)r * KVDIM + c * 8);
                CPA16(sb + AVL + sw256(r, c), vl + (size_t)r * KVDIM + c * 8);
            }
            asm volatile("cp.async.commit_group;");
            asm volatile("cp.async.wait_group 0;" ::: "memory");
            __syncthreads();
        }

        // ---- QK^T with 3-term split ----
        float sc[4][4];
        #pragma unroll
        for (int j = 0; j < 4; j++)
            #pragma unroll
            for (int q = 0; q < 4; q++) sc[j][q] = 0.f;

        #pragma unroll
        for (int ks = 0; ks < 8; ks++) {
            int c = ks * 2 + fhi;
            uint32_t ah[4], al[4];
            ldsm_x4(ah, sb + AQH + sw256(wm * 16 + frow, c));
            ldsm_x4(al, sb + AQL + sw256(wm * 16 + frow, c));
            #pragma unroll
            for (int g = 0; g < 2; g++) {
                uint32_t bh[4], bl[4];
                ldsm_x4(bh, sb + AKH + sw256(wn * 32 + g * 16 + frow, c));
                ldsm_x4(bl, sb + AKL + sw256(wn * 32 + g * 16 + frow, c));
                mma_16816(sc[g*2],   ah, bh[0], bh[2]);
                mma_16816(sc[g*2],   al, bh[0], bh[2]);
                mma_16816(sc[g*2],   ah, bl[0], bl[2]);
                mma_16816(sc[g*2+1], ah, bh[1], bh[3]);
                mma_16816(sc[g*2+1], al, bh[1], bh[3]);
                mma_16816(sc[g*2+1], ah, bl[1], bl[3]);
            }
        }

        // ---- scores -> smem fp32 ----
        {
            int r0 = wm * 16 + (lane >> 2);
            #pragma unroll
            for (int j = 0; j < 4; j++) {
                int col = wn * 32 + j * 8 + (lane & 3) * 2;
                *(float2*)(Ps + r0 * 68 + col)       = make_float2(sc[j][0], sc[j][1]);
                *(float2*)(Ps + (r0 + 8) * 68 + col) = make_float2(sc[j][2], sc[j][3]);
            }
        }
        __syncthreads();

        // ---- online softmax: 4 threads per row; P -> hi/lo bf16 tiles ----
        {
            int r = tid >> 2, seg = tid & 3;
            float p[16];
            #pragma unroll
            for (int i4 = 0; i4 < 4; i4++) {
                float4 v = *(float4*)(Ps + r * 68 + seg * 16 + i4 * 4);
                p[i4*4+0] = v.x; p[i4*4+1] = v.y; p[i4*4+2] = v.z; p[i4*4+3] = v.w;
            }
            if (jt == iq) {
                #pragma unroll
                for (int i = 0; i < 16; i++)
                    if (seg * 16 + i > r) p[i] = -3.0e38f;
            }
            float mx = p[0];
            #pragma unroll
            for (int i = 1; i < 16; i++) mx = fmaxf(mx, p[i]);
            mx = fmaxf(mx, __shfl_xor_sync(0xFFFFFFFF, mx, 1));
            mx = fmaxf(mx, __shfl_xor_sync(0xFFFFFFFF, mx, 2));
            float m_old = row_m[r];
            float mnew = fmaxf(m_old, mx);
            float cf = __expf(m_old - mnew);
            float sum = 0.f;
            #pragma unroll
            for (int i = 0; i < 16; i++) { p[i] = __expf(p[i] - mnew); sum += p[i]; }
            sum += __shfl_xor_sync(0xFFFFFFFF, sum, 1);
            sum += __shfl_xor_sync(0xFFFFFFFF, sum, 2);
            if ((tid & 3) == 0) {
                row_m[r] = mnew;
                row_l[r] = row_l[r] * cf + sum;
                row_cf[r] = cf;
            }
            // pack P hi/lo -> bf16 swizzled
            uint32_t ph[8], pl[8];
            #pragma unroll
            for (int i = 0; i < 8; i++) {
                __nv_bfloat16 h0 = __float2bfloat16(p[i*2]);
                __nv_bfloat16 h1 = __float2bfloat16(p[i*2+1]);
                __nv_bfloat162 th, tl;
                th.x = h0; th.y = h1;
                tl.x = __float2bfloat16(p[i*2]   - __bfloat162float(h0));
                tl.y = __float2bfloat16(p[i*2+1] - __bfloat162float(h1));
                ph[i] = *(uint32_t*)&th;
                pl[i] = *(uint32_t*)&tl;
            }
            uint32_t d0 = sb + APB + sw128(r, seg * 2);
            uint32_t d1 = sb + APB + sw128(r, seg * 2 + 1);
            uint32_t e0 = sb + APL + sw128(r, seg * 2);
            uint32_t e1 = sb + APL + sw128(r, seg * 2 + 1);
            asm volatile("st.shared.v4.b32 [%0], {%1,%2,%3,%4};"
                         :: "r"(d0), "r"(ph[0]), "r"(ph[1]), "r"(ph[2]), "r"(ph[3]));
            asm volatile("st.shared.v4.b32 [%0], {%1,%2,%3,%4};"
                         :: "r"(d1), "r"(ph[4]), "r"(ph[5]), "r"(ph[6]), "r"(ph[7]));
            asm volatile("st.shared.v4.b32 [%0], {%1,%2,%3,%4};"
                         :: "r"(e0), "r"(pl[0]), "r"(pl[1]), "r"(pl[2]), "r"(pl[3]));
            asm volatile("st.shared.v4.b32 [%0], {%1,%2,%3,%4};"
                         :: "r"(e1), "r"(pl[4]), "r"(pl[5]), "r"(pl[6]), "r"(pl[7]));
        }
        __syncthreads();

        // ---- rescale O, then O += P @ V with 3-term split ----
        {
            float cf0 = row_cf[wm * 16 + (lane >> 2)];
            float cf1 = row_cf[wm * 16 + 8 + (lane >> 2)];
            #pragma unroll
            for (int j = 0; j < 8; j++) {
                o[j][0] *= cf0; o[j][1] *= cf0;
                o[j][2] *= cf1; o[j][3] *= cf1;
            }
        }
        #pragma unroll
        for (int kc = 0; kc < 4; kc++) {
            uint32_t aph[4], apl[4];
            ldsm_x4(aph, sb + APB + sw128(wm * 16 + frow, kc * 2 + fhi));
            ldsm_x4(apl, sb + APL + sw128(wm * 16 + frow, kc * 2 + fhi));
            int t  = kc * 16 + ((lane >> 3) & 1) * 8 + (lane & 7);
            int cd = ((wn * 64) >> 3) + (lane >> 4);
            #pragma unroll
            for (int g = 0; g < 4; g++) {
                uint32_t bvh[4], bvl[4];
                ldsm_x4_t(bvh, sb + AVH + sw256(t, cd + g * 2));
                ldsm_x4_t(bvl, sb + AVL + sw256(t, cd + g * 2));
                mma_16816(o[g*2],   aph, bvh[0], bvh[1]);
                mma_16816(o[g*2],   apl, bvh[0], bvh[1]);
                mma_16816(o[g*2],   aph, bvl[0], bvl[1]);
                mma_16816(o[g*2+1], aph, bvh[2], bvh[3]);
                mma_16816(o[g*2+1], apl, bvh[2], bvh[3]);
                mma_16816(o[g*2+1], aph, bvl[2], bvl[3]);
            }
        }
        __syncthreads();
    }

    // ---- epilogue ----
    {
        int rr = lane >> 2;
        float invl0 = 1.f / row_l[wm * 16 + rr];
        float invl1 = 1.f / row_l[wm * 16 + 8 + rr];
        float* og = g_attn + ((size_t)(b * S_LEN + iq * 64 + wm * 16 + rr)) * EMB + h * HD;
        #pragma unroll
        for (int j = 0; j < 8; j++) {
            int col = wn * 64 + j * 8 + (lane & 3) * 2;
            *(float2*)(og + col)            = make_float2(o[j][0]*invl0, o[j][1]*invl0);
            *(float2*)(og + 8*EMB + col)    = make_float2(o[j][2]*invl1, o[j][3]*invl1);
        }
    }
}

// ----------------------------------------------------------------------------
// Launch
// ----------------------------------------------------------------------------
extern "C" void kernel_launch(void* const* d_in, const int* in_sizes, int n_in,
                              void* d_out, int out_size)
{
    const float* x  = (const float*)d_in[0];
    const float* Wq = (const float*)d_in[1];
    const float* Wk = (const float*)d_in[2];
    const float* Wv = (const float*)d_in[3];
    const float* Wo = (const float*)d_in[4];
    float* out = (float*)d_out;

    float *qp, *kp, *vp, *ap;
    __nv_bfloat16 *x2, *a2, *wq2, *wk2, *wv2, *wo2;
    __nv_bfloat16 *qh, *ql, *kh, *kl, *vh, *vl;
    cudaGetSymbolAddress((void**)&qp, g_q);
    cudaGetSymbolAddress((void**)&kp, g_k);
    cudaGetSymbolAddress((void**)&vp, g_v);
    cudaGetSymbolAddress((void**)&ap, g_attn);
    cudaGetSymbolAddress((void**)&x2, g_x2);
    cudaGetSymbolAddress((void**)&a2, g_a2);
    cudaGetSymbolAddress((void**)&wq2, g_wq2);
    cudaGetSymbolAddress((void**)&wk2, g_wk2);
    cudaGetSymbolAddress((void**)&wv2, g_wv2);
    cudaGetSymbolAddress((void**)&wo2, g_wo2);
    cudaGetSymbolAddress((void**)&qh, g_qh);
    cudaGetSymbolAddress((void**)&ql, g_ql);
    cudaGetSymbolAddress((void**)&kh, g_kh);
    cudaGetSymbolAddress((void**)&kl, g_kl);
    cudaGetSymbolAddress((void**)&vh, g_vh);
    cudaGetSymbolAddress((void**)&vl, g_vl);

    cudaFuncSetAttribute(gemm_mma, cudaFuncAttributeMaxDynamicSharedMemorySize, GEMM_SMEM);
    cudaFuncSetAttribute(attn_mma, cudaFuncAttributeMaxDynamicSharedMemorySize, ATT_SMEM);

    // GEMM operand splits
    {
        int t4 = MROWS * EMB / 4;
        split_hl<<<(t4 + 255) / 256, 256>>>(x, x2, EMB, t4, 0);
        t4 = EMB * EMB / 4;
        split_hl<<<(t4 + 255) / 256, 256>>>(Wq, wq2, EMB, t4, 1);
        split_hl<<<(t4 + 255) / 256, 256>>>(Wo, wo2, EMB, t4, 1);
        t4 = KVDIM * EMB / 4;
        split_hl<<<(t4 + 255) / 256, 256>>>(Wk, wk2, EMB, t4, 1);
        split_hl<<<(t4 + 255) / 256, 256>>>(Wv, wv2, EMB, t4, 1);
    }

    dim3 gq(EMB / 128, MROWS / 128);
    dim3 gkv(KVDIM / 128, MROWS / 128);

    gemm_mma<<<gq,  256, GEMM_SMEM>>>(x2, wq2, qp, MROWS, EMB,   K2);
    gemm_mma<<<gkv, 256, GEMM_SMEM>>>(x2, wk2, kp, MROWS, KVDIM, K2);
    gemm_mma<<<gkv, 256, GEMM_SMEM>>>(x2, wv2, vp, MROWS, KVDIM, K2);

    // attention operand conversion (hi/lo for q, k, v)
    {
        const float qscale = 0.08838834764831845f;  // 1/sqrt(128)
        int t4 = MROWS * EMB / 4;
        split2<<<(t4 + 255) / 256, 256>>>(qp, qh, ql, qscale, t4);
        t4 = MROWS * KVDIM / 4;
        split2<<<(t4 + 255) / 256, 256>>>(kp, kh, kl, 1.0f, t4);
        split2<<<(t4 + 255) / 256, 256>>>(vp, vh, vl, 1.0f, t4);
    }

    dim3 ga(S_LEN / 64, NH, BATCH);   // (32, 16, 2)
    attn_mma<<<ga, 256, ATT_SMEM>>>();

    {
        int t4 = MROWS * EMB / 4;
        split_hl<<<(t4 + 255) / 256, 256>>>(ap, a2, EMB, t4, 0);
    }
    gemm_mma<<<gq, 256, GEMM_SMEM>>>(a2, wo2, out, MROWS, EMB, K2);
}

// round 7
// speedup vs baseline: 3.3100x; 1.0401x over previous
#include <cuda_runtime.h>
#include <cuda_bf16.h>
#include <cstdint>
#include <math.h>

#define S_LEN 2048
#define BATCH 2
#define EMB   2048
#define NH    16
#define NKV   4
#define HD    128
#define KVDIM (NKV*HD)        // 512
#define KVS   (2*KVDIM)       // 1024: fused K|V projection width
#define MROWS (BATCH*S_LEN)   // 4096

// ---------------- scratch (allocation-free) ----------------
__device__ __nv_bfloat16 g_xh[(size_t)MROWS * EMB];
__device__ __nv_bfloat16 g_xl[(size_t)MROWS * EMB];
__device__ __nv_bfloat16 g_wqh[(size_t)EMB * EMB];
__device__ __nv_bfloat16 g_wql[(size_t)EMB * EMB];
__device__ __nv_bfloat16 g_woh[(size_t)EMB * EMB];
__device__ __nv_bfloat16 g_wol[(size_t)EMB * EMB];
__device__ __nv_bfloat16 g_wkvh[(size_t)KVS * EMB];
__device__ __nv_bfloat16 g_wkvl[(size_t)KVS * EMB];
__device__ __nv_bfloat16 g_qh[(size_t)MROWS * EMB];
__device__ __nv_bfloat16 g_ql[(size_t)MROWS * EMB];
__device__ __nv_bfloat16 g_kvh[(size_t)MROWS * KVS];
__device__ __nv_bfloat16 g_kvl[(size_t)MROWS * KVS];
__device__ __nv_bfloat16 g_ah[(size_t)MROWS * EMB];
__device__ __nv_bfloat16 g_al[(size_t)MROWS * EMB];

// ---------------- common MMA helpers ----------------
__device__ __forceinline__ void ldsm_x4(uint32_t* r, uint32_t addr) {
    asm volatile("ldmatrix.sync.aligned.m8n8.x4.shared.b16 {%0,%1,%2,%3}, [%4];"
                 : "=r"(r[0]), "=r"(r[1]), "=r"(r[2]), "=r"(r[3]) : "r"(addr));
}
__device__ __forceinline__ void ldsm_x4_t(uint32_t* r, uint32_t addr) {
    asm volatile("ldmatrix.sync.aligned.m8n8.x4.trans.shared.b16 {%0,%1,%2,%3}, [%4];"
                 : "=r"(r[0]), "=r"(r[1]), "=r"(r[2]), "=r"(r[3]) : "r"(addr));
}
__device__ __forceinline__ void mma_16816(float* d, const uint32_t* a, uint32_t b0,
                                          uint32_t b1) {
    asm volatile(
        "mma.sync.aligned.m16n8k16.row.col.f32.bf16.bf16.f32 "
        "{%0,%1,%2,%3}, {%4,%5,%6,%7}, {%8,%9}, {%0,%1,%2,%3};"
        : "+f"(d[0]), "+f"(d[1]), "+f"(d[2]), "+f"(d[3])
        : "r"(a[0]), "r"(a[1]), "r"(a[2]), "r"(a[3]), "r"(b0), "r"(b1));
}
#define CPA16(dst, src) \
    asm volatile("cp.async.cg.shared.global [%0], [%1], 16;" :: "r"(dst), "l"(src))

__device__ __forceinline__ uint32_t pack_bf2(float a, float b) {
    __nv_bfloat162 t;
    t.x = __float2bfloat16(a); t.y = __float2bfloat16(b);
    return *(uint32_t*)&t;
}

// ----------------------------------------------------------------------------
// vectorized split: fp32 -> hi bf16 + lo bf16, 8 elems/thread, 16B stores
// ----------------------------------------------------------------------------
__global__ __launch_bounds__(256) void split2v(const float* __restrict__ in,
                                               __nv_bfloat16* __restrict__ hi,
                                               __nv_bfloat16* __restrict__ lo,
                                               int total8)
{
    int i = blockIdx.x * blockDim.x + threadIdx.x;
    if (i >= total8) return;
    const float4* p = (const float4*)(in + (size_t)i * 8);
    float4 a = p[0], b = p[1];
    float f[8] = {a.x, a.y, a.z, a.w, b.x, b.y, b.z, b.w};
    uint32_t H[4], L[4];
    #pragma unroll
    for (int j = 0; j < 4; j++) {
        __nv_bfloat16 h0 = __float2bfloat16(f[j*2]);
        __nv_bfloat16 h1 = __float2bfloat16(f[j*2+1]);
        __nv_bfloat162 th, tl;
        th.x = h0; th.y = h1;
        tl.x = __float2bfloat16(f[j*2]   - __bfloat162float(h0));
        tl.y = __float2bfloat16(f[j*2+1] - __bfloat162float(h1));
        H[j] = *(uint32_t*)&th;
        L[j] = *(uint32_t*)&tl;
    }
    *(uint4*)(hi + (size_t)i * 8) = make_uint4(H[0], H[1], H[2], H[3]);
    *(uint4*)(lo + (size_t)i * 8) = make_uint4(L[0], L[1], L[2], L[3]);
}

// ----------------------------------------------------------------------------
// 4-pointer hi/lo HMMA GEMM: C = Ah.Bh^T + Al.Bh^T + Ah.Bl^T  (K = 2048)
// CTA 128x128, BK=64, 3-stage cp.async (64KB/stage), 8 warps (4m x 2n).
// Epilogue: fp32 to Cf, OR bf16 hi/lo pair to Ch/Cl with scale.
// ----------------------------------------------------------------------------
#define GST 65536
#define GEMM_SMEM (3 * GST)

__global__ __launch_bounds__(256, 1) void gemm_hl(
    const __nv_bfloat16* __restrict__ Ah, const __nv_bfloat16* __restrict__ Al,
    const __nv_bfloat16* __restrict__ Bh, const __nv_bfloat16* __restrict__ Bl,
    float* __restrict__ Cf,
    __nv_bfloat16* __restrict__ Ch, __nv_bfloat16* __restrict__ Cl,
    float scale, int M, int N, int K)
{
    extern __shared__ __align__(1024) char smem[];
    const uint32_t sbase = (uint32_t)__cvta_generic_to_shared(smem);

    const int tid  = threadIdx.x;
    const int warp = tid >> 5, lane = tid & 31;
    const int wm   = warp & 3, wn = warp >> 2;
    const int brow = blockIdx.y * 128, bcol = blockIdx.x * 128;

    const size_t dAl = (size_t)(Al - Ah);
    const size_t dBl = (size_t)(Bl - Bh);

    uint32_t dstA[4];
    const __nv_bfloat16* srcA[4];
    const __nv_bfloat16* srcB[4];
    #pragma unroll
    for (int it = 0; it < 4; it++) {
        int id  = it * 256 + tid;
        int row = id >> 3, c = id & 7;
        dstA[it] = sbase + row * 128 + ((c ^ (row & 7)) * 16);
        srcA[it] = Ah + (size_t)(brow + row) * K + c * 8;
        srcB[it] = Bh + (size_t)(bcol + row) * K + c * 8;
    }

    const int NT = K / 64;   // 32

    #define LOAD_STAGE(s, kt) do {                                             \
        uint32_t so = (uint32_t)(s) * GST;                                     \
        int ko = (kt) * 64;                                                    \
        _Pragma("unroll")                                                      \
        for (int it = 0; it < 4; it++) {                                       \
            CPA16(dstA[it] + so,         srcA[it] + ko);                       \
            CPA16(dstA[it] + so + 16384, srcA[it] + dAl + ko);                 \
            CPA16(dstA[it] + so + 32768, srcB[it] + ko);                       \
            CPA16(dstA[it] + so + 49152, srcB[it] + dBl + ko);                 \
        }                                                                      \
        asm volatile("cp.async.commit_group;");                                \
    } while (0)

    LOAD_STAGE(0, 0);
    LOAD_STAGE(1, 1);
    LOAD_STAGE(2, 2);

    float acc[2][8][4];
    #pragma unroll
    for (int i = 0; i < 2; i++)
        #pragma unroll
        for (int j = 0; j < 8; j++)
            #pragma unroll
            for (int q = 0; q < 4; q++) acc[i][j][q] = 0.f;

    const int frow = lane & 15;
    const int fhi  = lane >> 4;

    for (int kt = 0; kt < NT; kt++) {
        int s = kt % 3;
        asm volatile("cp.async.wait_group 2;" ::: "memory");
        __syncthreads();

        uint32_t ab = sbase + s * GST;

        #pragma unroll
        for (int ks = 0; ks < 4; ks++) {
            int c = ks * 2 + fhi;
            uint32_t ah[2][4], al[2][4], bh[4][4], bl[4][4];
            #pragma unroll
            for (int i = 0; i < 2; i++) {
                int row = wm * 32 + i * 16 + frow;
                uint32_t sw = row * 128 + ((c ^ (row & 7)) * 16);
                ldsm_x4(ah[i], ab + sw);
                ldsm_x4(al[i], ab + 16384 + sw);
            }
            #pragma unroll
            for (int g = 0; g < 4; g++) {
                int row = wn * 64 + g * 16 + frow;
                uint32_t sw = row * 128 + ((c ^ (row & 7)) * 16);
                ldsm_x4(bh[g], ab + 32768 + sw);
                ldsm_x4(bl[g], ab + 49152 + sw);
            }
            #pragma unroll
            for (int i = 0; i < 2; i++)
                #pragma unroll
                for (int j = 0; j < 8; j++) {
                    int g = j >> 1, p = j & 1;
                    mma_16816(acc[i][j], ah[i], bh[g][p], bh[g][p+2]);
                    mma_16816(acc[i][j], al[i], bh[g][p], bh[g][p+2]);
                    mma_16816(acc[i][j], ah[i], bl[g][p], bl[g][p+2]);
                }
        }
        __syncthreads();
        if (kt + 3 < NT) { LOAD_STAGE(s, kt + 3); }
        else { asm volatile("cp.async.commit_group;"); }
    }

    const int erow = lane >> 2;
    const int ecol = (lane & 3) * 2;
    if (Cf) {
        #pragma unroll
        for (int i = 0; i < 2; i++) {
            int r0 = brow + wm * 32 + i * 16 + erow;
            #pragma unroll
            for (int j = 0; j < 8; j++) {
                int cc = bcol + wn * 64 + j * 8 + ecol;
                *(float2*)(Cf + (size_t)r0 * N + cc) =
                    make_float2(acc[i][j][0], acc[i][j][1]);
                *(float2*)(Cf + (size_t)(r0 + 8) * N + cc) =
                    make_float2(acc[i][j][2], acc[i][j][3]);
            }
        }
    } else {
        #pragma unroll
        for (int i = 0; i < 2; i++) {
            int r0 = brow + wm * 32 + i * 16 + erow;
            #pragma unroll
            for (int j = 0; j < 8; j++) {
                int cc = bcol + wn * 64 + j * 8 + ecol;
                #pragma unroll
                for (int half = 0; half < 2; half++) {
                    size_t idx = (size_t)(r0 + half * 8) * N + cc;
                    float v0 = acc[i][j][half*2]   * scale;
                    float v1 = acc[i][j][half*2+1] * scale;
                    __nv_bfloat16 h0 = __float2bfloat16(v0);
                    __nv_bfloat16 h1 = __float2bfloat16(v1);
                    __nv_bfloat162 th, tl;
                    th.x = h0; th.y = h1;
                    tl.x = __float2bfloat16(v0 - __bfloat162float(h0));
                    tl.y = __float2bfloat16(v1 - __bfloat162float(h1));
                    *(__nv_bfloat162*)(Ch + idx) = th;
                    *(__nv_bfloat162*)(Cl + idx) = tl;
                }
            }
        }
    }
    #undef LOAD_STAGE
}

// ----------------------------------------------------------------------------
// HMMA flash attention: causal, GQA. Full hi/lo split on QK AND PV.
// K/V come from fused kv arrays (row stride KVS=1024, V at +512).
// Epilogue writes bf16 hi/lo directly (feeds O-projection).
// ----------------------------------------------------------------------------
#define AQH 0
#define AQL 16384
#define AKH 32768
#define AKL 49152
#define AVH 65536
#define AVL 81920
#define APS 98304
#define APB (APS + 64*68*4)
#define APL (APB + 8192)
#define AST (APL + 8192)
#define ATT_SMEM (AST + 64*4*3)

__device__ __forceinline__ uint32_t sw256(int r, int c) {
    return (uint32_t)(r * 256 + (((c & 7) ^ (r & 7)) | (c & 8)) * 16);
}
__device__ __forceinline__ uint32_t sw128(int r, int c) {
    return (uint32_t)(r * 128 + ((c ^ (r & 7)) * 16));
}

__global__ __launch_bounds__(256, 1) void attn_mma()
{
    extern __shared__ __align__(1024) char smraw[];
    const uint32_t sb = (uint32_t)__cvta_generic_to_shared(smraw);
    float* Ps     = (float*)(smraw + APS);
    float* row_m  = (float*)(smraw + AST);
    float* row_l  = row_m + 64;
    float* row_cf = row_l + 64;

    const int tid  = threadIdx.x;
    const int warp = tid >> 5, lane = tid & 31;
    const int wm   = warp & 3, wn = warp >> 2;
    const int frow = lane & 15, fhi = lane >> 4;
    const int iq   = blockIdx.x;
    const int h    = blockIdx.y;
    const int b    = blockIdx.z;
    const int kvhead = h / (NH / NKV);

    {
        const __nv_bfloat16* qh = g_qh + ((size_t)(b * S_LEN + iq * 64)) * EMB + h * HD;
        const __nv_bfloat16* ql = g_ql + ((size_t)(b * S_LEN + iq * 64)) * EMB + h * HD;
        #pragma unroll
        for (int it = 0; it < 4; it++) {
            int id = it * 256 + tid;
            int r = id >> 4, c = id & 15;
            CPA16(sb + AQH + sw256(r, c), qh + (size_t)r * EMB + c * 8);
            CPA16(sb + AQL + sw256(r, c), ql + (size_t)r * EMB + c * 8);
        }
        asm volatile("cp.async.commit_group;");
    }
    if (tid < 64) { row_m[tid] = -3.0e38f; row_l[tid] = 0.f; }

    float o[8][4];
    #pragma unroll
    for (int j = 0; j < 8; j++)
        #pragma unroll
        for (int q = 0; q < 4; q++) o[j][q] = 0.f;

    asm volatile("cp.async.wait_group 0;" ::: "memory");
    __syncthreads();

    const __nv_bfloat16* khb = g_kvh + ((size_t)(b * S_LEN)) * KVS + kvhead * HD;
    const __nv_bfloat16* klb = g_kvl + ((size_t)(b * S_LEN)) * KVS + kvhead * HD;
    const __nv_bfloat16* vhb = khb + KVDIM;
    const __nv_bfloat16* vlb = klb + KVDIM;

    for (int jt = 0; jt <= iq; jt++) {
        {
            const __nv_bfloat16* kh = khb + (size_t)(jt * 64) * KVS;
            const __nv_bfloat16* kl = klb + (size_t)(jt * 64) * KVS;
            const __nv_bfloat16* vh = vhb + (size_t)(jt * 64) * KVS;
            const __nv_bfloat16* vl = vlb + (size_t)(jt * 64) * KVS;
            #pragma unroll
            for (int it = 0; it < 4; it++) {
                int id = it * 256 + tid;
                int r = id >> 4, c = id & 15;
                CPA16(sb + AKH + sw256(r, c), kh + (size_t)r * KVS + c * 8);
                CPA16(sb + AKL + sw256(r, c), kl + (size_t)r * KVS + c * 8);
                CPA16(sb + AVH + sw256(r, c), vh + (size_t)r * KVS + c * 8);
                CPA16(sb + AVL + sw256(r, c), vl + (size_t)r * KVS + c * 8);
            }
            asm volatile("cp.async.commit_group;");
            asm volatile("cp.async.wait_group 0;" ::: "memory");
            __syncthreads();
        }

        float sc[4][4];
        #pragma unroll
        for (int j = 0; j < 4; j++)
            #pragma unroll
            for (int q = 0; q < 4; q++) sc[j][q] = 0.f;

        #pragma unroll
        for (int ks = 0; ks < 8; ks++) {
            int c = ks * 2 + fhi;
            uint32_t ah[4], al[4];
            ldsm_x4(ah, sb + AQH + sw256(wm * 16 + frow, c));
            ldsm_x4(al, sb + AQL + sw256(wm * 16 + frow, c));
            #pragma unroll
            for (int g = 0; g < 2; g++) {
                uint32_t bh[4], bl[4];
                ldsm_x4(bh, sb + AKH + sw256(wn * 32 + g * 16 + frow, c));
                ldsm_x4(bl, sb + AKL + sw256(wn * 32 + g * 16 + frow, c));
                mma_16816(sc[g*2],   ah, bh[0], bh[2]);
                mma_16816(sc[g*2],   al, bh[0], bh[2]);
                mma_16816(sc[g*2],   ah, bl[0], bl[2]);
                mma_16816(sc[g*2+1], ah, bh[1], bh[3]);
                mma_16816(sc[g*2+1], al, bh[1], bh[3]);
                mma_16816(sc[g*2+1], ah, bl[1], bl[3]);
            }
        }

        {
            int r0 = wm * 16 + (lane >> 2);
            #pragma unroll
            for (int j = 0; j < 4; j++) {
                int col = wn * 32 + j * 8 + (lane & 3) * 2;
                *(float2*)(Ps + r0 * 68 + col)       = make_float2(sc[j][0], sc[j][1]);
                *(float2*)(Ps + (r0 + 8) * 68 + col) = make_float2(sc[j][2], sc[j][3]);
            }
        }
        __syncthreads();

        {
            int r = tid >> 2, seg = tid & 3;
            float p[16];
            #pragma unroll
            for (int i4 = 0; i4 < 4; i4++) {
                float4 v = *(float4*)(Ps + r * 68 + seg * 16 + i4 * 4);
                p[i4*4+0] = v.x; p[i4*4+1] = v.y; p[i4*4+2] = v.z; p[i4*4+3] = v.w;
            }
            if (jt == iq) {
                #pragma unroll
                for (int i = 0; i < 16; i++)
                    if (seg * 16 + i > r) p[i] = -3.0e38f;
            }
            float mx = p[0];
            #pragma unroll
            for (int i = 1; i < 16; i++) mx = fmaxf(mx, p[i]);
            mx = fmaxf(mx, __shfl_xor_sync(0xFFFFFFFF, mx, 1));
            mx = fmaxf(mx, __shfl_xor_sync(0xFFFFFFFF, mx, 2));
            float m_old = row_m[r];
            float mnew = fmaxf(m_old, mx);
            float cf = __expf(m_old - mnew);
            float sum = 0.f;
            #pragma unroll
            for (int i = 0; i < 16; i++) { p[i] = __expf(p[i] - mnew); sum += p[i]; }
            sum += __shfl_xor_sync(0xFFFFFFFF, sum, 1);
            sum += __shfl_xor_sync(0xFFFFFFFF, sum, 2);
            if ((tid & 3) == 0) {
                row_m[r] = mnew;
                row_l[r] = row_l[r] * cf + sum;
                row_cf[r] = cf;
            }
            uint32_t ph[8], pl[8];
            #pragma unroll
            for (int i = 0; i < 8; i++) {
                __nv_bfloat16 h0 = __float2bfloat16(p[i*2]);
                __nv_bfloat16 h1 = __float2bfloat16(p[i*2+1]);
                __nv_bfloat162 th, tl;
                th.x = h0; th.y = h1;
                tl.x = __float2bfloat16(p[i*2]   - __bfloat162float(h0));
                tl.y = __float2bfloat16(p[i*2+1] - __bfloat162float(h1));
                ph[i] = *(uint32_t*)&th;
                pl[i] = *(uint32_t*)&tl;
            }
            uint32_t d0 = sb + APB + sw128(r, seg * 2);
            uint32_t d1 = sb + APB + sw128(r, seg * 2 + 1);
            uint32_t e0 = sb + APL + sw128(r, seg * 2);
            uint32_t e1 = sb + APL + sw128(r, seg * 2 + 1);
            asm volatile("st.shared.v4.b32 [%0], {%1,%2,%3,%4};"
                         :: "r"(d0), "r"(ph[0]), "r"(ph[1]), "r"(ph[2]), "r"(ph[3]));
            asm volatile("st.shared.v4.b32 [%0], {%1,%2,%3,%4};"
                         :: "r"(d1), "r"(ph[4]), "r"(ph[5]), "r"(ph[6]), "r"(ph[7]));
            asm volatile("st.shared.v4.b32 [%0], {%1,%2,%3,%4};"
                         :: "r"(e0), "r"(pl[0]), "r"(pl[1]), "r"(pl[2]), "r"(pl[3]));
            asm volatile("st.shared.v4.b32 [%0], {%1,%2,%3,%4};"
                         :: "r"(e1), "r"(pl[4]), "r"(pl[5]), "r"(pl[6]), "r"(pl[7]));
        }
        __syncthreads();

        {
            float cf0 = row_cf[wm * 16 + (lane >> 2)];
            float cf1 = row_cf[wm * 16 + 8 + (lane >> 2)];
            #pragma unroll
            for (int j = 0; j < 8; j++) {
                o[j][0] *= cf0; o[j][1] *= cf0;
                o[j][2] *= cf1; o[j][3] *= cf1;
            }
        }
        #pragma unroll
        for (int kc = 0; kc < 4; kc++) {
            uint32_t aph[4], apl[4];
            ldsm_x4(aph, sb + APB + sw128(wm * 16 + frow, kc * 2 + fhi));
            ldsm_x4(apl, sb + APL + sw128(wm * 16 + frow, kc * 2 + fhi));
            int t  = kc * 16 + ((lane >> 3) & 1) * 8 + (lane & 7);
            int cd = ((wn * 64) >> 3) + (lane >> 4);
            #pragma unroll
            for (int g = 0; g < 4; g++) {
                uint32_t bvh[4], bvl[4];
                ldsm_x4_t(bvh, sb + AVH + sw256(t, cd + g * 2));
                ldsm_x4_t(bvl, sb + AVL + sw256(t, cd + g * 2));
                mma_16816(o[g*2],   aph, bvh[0], bvh[1]);
                mma_16816(o[g*2],   apl, bvh[0], bvh[1]);
                mma_16816(o[g*2],   aph, bvl[0], bvl[1]);
                mma_16816(o[g*2+1], aph, bvh[2], bvh[3]);
                mma_16816(o[g*2+1], apl, bvh[2], bvh[3]);
                mma_16816(o[g*2+1], aph, bvl[2], bvl[3]);
            }
        }
        __syncthreads();
    }

    // ---- epilogue: normalize + bf16 hi/lo write (feeds O-projection) ----
    {
        int rr = lane >> 2;
        float invl0 = 1.f / row_l[wm * 16 + rr];
        float invl1 = 1.f / row_l[wm * 16 + 8 + rr];
        size_t base = ((size_t)(b * S_LEN + iq * 64 + wm * 16 + rr)) * EMB + h * HD;
        #pragma unroll
        for (int j = 0; j < 8; j++) {
            int col = wn * 64 + j * 8 + (lane & 3) * 2;
            float v0 = o[j][0] * invl0, v1 = o[j][1] * invl0;
            float v2 = o[j][2] * invl1, v3 = o[j][3] * invl1;
            __nv_bfloat16 h0 = __float2bfloat16(v0), h1 = __float2bfloat16(v1);
            __nv_bfloat16 h2 = __float2bfloat16(v2), h3 = __float2bfloat16(v3);
            __nv_bfloat162 th0, th1, tl0, tl1;
            th0.x = h0; th0.y = h1; th1.x = h2; th1.y = h3;
            tl0.x = __float2bfloat16(v0 - __bfloat162float(h0));
            tl0.y = __float2bfloat16(v1 - __bfloat162float(h1));
            tl1.x = __float2bfloat16(v2 - __bfloat162float(h2));
            tl1.y = __float2bfloat16(v3 - __bfloat162float(h3));
            *(__nv_bfloat162*)(g_ah + base + col)           = th0;
            *(__nv_bfloat162*)(g_al + base + col)           = tl0;
            *(__nv_bfloat162*)(g_ah + base + 8*EMB + col)   = th1;
            *(__nv_bfloat162*)(g_al + base + 8*EMB + col)   = tl1;
        }
    }
}

// ----------------------------------------------------------------------------
// Launch
// ----------------------------------------------------------------------------
extern "C" void kernel_launch(void* const* d_in, const int* in_sizes, int n_in,
                              void* d_out, int out_size)
{
    const float* x  = (const float*)d_in[0];
    const float* Wq = (const float*)d_in[1];
    const float* Wk = (const float*)d_in[2];
    const float* Wv = (const float*)d_in[3];
    const float* Wo = (const float*)d_in[4];
    float* out = (float*)d_out;

    __nv_bfloat16 *xh, *xl, *wqh, *wql, *woh, *wol, *wkvh, *wkvl;
    __nv_bfloat16 *qh, *ql, *kvh, *kvl, *ah, *al;
    cudaGetSymbolAddress((void**)&xh, g_xh);
    cudaGetSymbolAddress((void**)&xl, g_xl);
    cudaGetSymbolAddress((void**)&wqh, g_wqh);
    cudaGetSymbolAddress((void**)&wql, g_wql);
    cudaGetSymbolAddress((void**)&woh, g_woh);
    cudaGetSymbolAddress((void**)&wol, g_wol);
    cudaGetSymbolAddress((void**)&wkvh, g_wkvh);
    cudaGetSymbolAddress((void**)&wkvl, g_wkvl);
    cudaGetSymbolAddress((void**)&qh, g_qh);
    cudaGetSymbolAddress((void**)&ql, g_ql);
    cudaGetSymbolAddress((void**)&kvh, g_kvh);
    cudaGetSymbolAddress((void**)&kvl, g_kvl);
    cudaGetSymbolAddress((void**)&ah, g_ah);
    cudaGetSymbolAddress((void**)&al, g_al);

    cudaFuncSetAttribute(gemm_hl, cudaFuncAttributeMaxDynamicSharedMemorySize, GEMM_SMEM);
    cudaFuncSetAttribute(attn_mma, cudaFuncAttributeMaxDynamicSharedMemorySize, ATT_SMEM);

    // splits (vectorized): x, Wq, Wo, and Wk|Wv fused into one [1024,2048] weight
    {
        int t8 = MROWS * EMB / 8;
        split2v<<<t8 / 256, 256>>>(x, xh, xl, t8);
        t8 = EMB * EMB / 8;
        split2v<<<t8 / 256, 256>>>(Wq, wqh, wql, t8);
        split2v<<<t8 / 256, 256>>>(Wo, woh, wol, t8);
        t8 = KVDIM * EMB / 8;
        split2v<<<t8 / 256, 256>>>(Wk, wkvh, wkvl, t8);
        split2v<<<t8 / 256, 256>>>(Wv, wkvh + (size_t)KVDIM * EMB,
                                       wkvl + (size_t)KVDIM * EMB, t8);
    }

    const float qscale = 0.08838834764831845f;  // 1/sqrt(128)
    dim3 gq(EMB / 128, MROWS / 128);     // (16, 32)
    dim3 gkv(KVS / 128, MROWS / 128);    // (8, 32)

    // Q projection -> qh/ql (scaled); fused KV projection -> kvh/kvl
    gemm_hl<<<gq,  256, GEMM_SMEM>>>(xh, xl, wqh, wql, nullptr, qh, ql,
                                     qscale, MROWS, EMB, EMB);
    gemm_hl<<<gkv, 256, GEMM_SMEM>>>(xh, xl, wkvh, wkvl, nullptr, kvh, kvl,
                                     1.0f, MROWS, KVS, EMB);

    dim3 ga(S_LEN / 64, NH, BATCH);      // (32, 16, 2)
    attn_mma<<<ga, 256, ATT_SMEM>>>();

    // O projection (reads attention's bf16 hi/lo output directly) -> fp32 out
    gemm_hl<<<gq, 256, GEMM_SMEM>>>(ah, al, woh, wol, out, nullptr, nullptr,
                                    1.0f, MROWS, EMB, EMB);
}

// round 8
// speedup vs baseline: 3.5713x; 1.0789x over previous
#include <cuda_runtime.h>
#include <cuda_bf16.h>
#include <cstdint>
#include <math.h>

#define S_LEN 2048
#define BATCH 2
#define EMB   2048
#define NH    16
#define NKV   4
#define HD    128
#define KVDIM (NKV*HD)        // 512
#define KVS   (2*KVDIM)       // 1024
#define QKVN  (EMB + KVS)     // 3072: fused Q|K|V projection width
#define MROWS (BATCH*S_LEN)   // 4096

// ---------------- scratch (allocation-free) ----------------
__device__ __nv_bfloat16 g_xh[(size_t)MROWS * EMB];
__device__ __nv_bfloat16 g_xl[(size_t)MROWS * EMB];
__device__ __nv_bfloat16 g_wh[(size_t)QKVN * EMB];    // [Wq | Wk | Wv] hi
__device__ __nv_bfloat16 g_wl[(size_t)QKVN * EMB];    // lo
__device__ __nv_bfloat16 g_woh[(size_t)EMB * EMB];
__device__ __nv_bfloat16 g_wol[(size_t)EMB * EMB];
__device__ __nv_bfloat16 g_qh[(size_t)MROWS * EMB];
__device__ __nv_bfloat16 g_ql[(size_t)MROWS * EMB];
__device__ __nv_bfloat16 g_kvh[(size_t)MROWS * KVS];
__device__ __nv_bfloat16 g_kvl[(size_t)MROWS * KVS];
__device__ __nv_bfloat16 g_ah[(size_t)MROWS * EMB];
__device__ __nv_bfloat16 g_al[(size_t)MROWS * EMB];

// ---------------- common MMA helpers ----------------
__device__ __forceinline__ void ldsm_x4(uint32_t* r, uint32_t addr) {
    asm volatile("ldmatrix.sync.aligned.m8n8.x4.shared.b16 {%0,%1,%2,%3}, [%4];"
                 : "=r"(r[0]), "=r"(r[1]), "=r"(r[2]), "=r"(r[3]) : "r"(addr));
}
__device__ __forceinline__ void ldsm_x4_t(uint32_t* r, uint32_t addr) {
    asm volatile("ldmatrix.sync.aligned.m8n8.x4.trans.shared.b16 {%0,%1,%2,%3}, [%4];"
                 : "=r"(r[0]), "=r"(r[1]), "=r"(r[2]), "=r"(r[3]) : "r"(addr));
}
__device__ __forceinline__ void mma_16816(float* d, const uint32_t* a, uint32_t b0,
                                          uint32_t b1) {
    asm volatile(
        "mma.sync.aligned.m16n8k16.row.col.f32.bf16.bf16.f32 "
        "{%0,%1,%2,%3}, {%4,%5,%6,%7}, {%8,%9}, {%0,%1,%2,%3};"
        : "+f"(d[0]), "+f"(d[1]), "+f"(d[2]), "+f"(d[3])
        : "r"(a[0]), "r"(a[1]), "r"(a[2]), "r"(a[3]), "r"(b0), "r"(b1));
}
#define CPA16(dst, src) \
    asm volatile("cp.async.cg.shared.global [%0], [%1], 16;" :: "r"(dst), "l"(src))

// ----------------------------------------------------------------------------
// vectorized split: fp32 -> hi bf16 + lo bf16
// ----------------------------------------------------------------------------
__global__ __launch_bounds__(256) void split2v(const float* __restrict__ in,
                                               __nv_bfloat16* __restrict__ hi,
                                               __nv_bfloat16* __restrict__ lo,
                                               int total8)
{
    int i = blockIdx.x * blockDim.x + threadIdx.x;
    if (i >= total8) return;
    const float4* p = (const float4*)(in + (size_t)i * 8);
    float4 a = p[0], b = p[1];
    float f[8] = {a.x, a.y, a.z, a.w, b.x, b.y, b.z, b.w};
    uint32_t H[4], L[4];
    #pragma unroll
    for (int j = 0; j < 4; j++) {
        __nv_bfloat16 h0 = __float2bfloat16(f[j*2]);
        __nv_bfloat16 h1 = __float2bfloat16(f[j*2+1]);
        __nv_bfloat162 th, tl;
        th.x = h0; th.y = h1;
        tl.x = __float2bfloat16(f[j*2]   - __bfloat162float(h0));
        tl.y = __float2bfloat16(f[j*2+1] - __bfloat162float(h1));
        H[j] = *(uint32_t*)&th;
        L[j] = *(uint32_t*)&tl;
    }
    *(uint4*)(hi + (size_t)i * 8) = make_uint4(H[0], H[1], H[2], H[3]);
    *(uint4*)(lo + (size_t)i * 8) = make_uint4(L[0], L[1], L[2], L[3]);
}

// ----------------------------------------------------------------------------
// hi/lo HMMA GEMM, BK=32, 3 stages x 32KB smem -> 2 CTAs/SM.
// C = Ah.Bh^T + Al.Bh^T + Ah.Bl^T.  CTA 128x128, 8 warps (4m x 2n).
// mode 0: fp32 to Cf.  mode 1: fused QKV epilogue (bf16 hi/lo to globals,
//         q-region scaled by 'scale').
// 64B-row swizzle: chunk' = c ^ ((row>>1)&3)  (conflict-free for cp.async
// stores and all ldmatrix phases).
// ----------------------------------------------------------------------------
#define GST32 32768
#define GEMM_SMEM (3 * GST32)

__device__ __forceinline__ uint32_t sw64(int r, int c) {
    return (uint32_t)(r * 64 + ((c ^ ((r >> 1) & 3)) * 16));
}

__global__ __launch_bounds__(256, 2) void gemm_hl(
    const __nv_bfloat16* __restrict__ Ah, const __nv_bfloat16* __restrict__ Al,
    const __nv_bfloat16* __restrict__ Bh, const __nv_bfloat16* __restrict__ Bl,
    float* __restrict__ Cf, int mode, float scale, int M, int N, int K)
{
    extern __shared__ __align__(1024) char smem[];
    const uint32_t sbase = (uint32_t)__cvta_generic_to_shared(smem);

    const int tid  = threadIdx.x;
    const int warp = tid >> 5, lane = tid & 31;
    const int wm   = warp & 3, wn = warp >> 2;
    const int brow = blockIdx.y * 128, bcol = blockIdx.x * 128;

    const size_t dAl = (size_t)(Al - Ah);
    const size_t dBl = (size_t)(Bl - Bh);

    uint32_t dst[2];
    const __nv_bfloat16* sA[2];
    const __nv_bfloat16* sB[2];
    #pragma unroll
    for (int it = 0; it < 2; it++) {
        int id  = it * 256 + tid;
        int row = id >> 2, c = id & 3;
        dst[it] = sbase + sw64(row, c);
        sA[it]  = Ah + (size_t)(brow + row) * K + c * 8;
        sB[it]  = Bh + (size_t)(bcol + row) * K + c * 8;
    }

    const int NT = K / 32;   // 64

    #define LOAD_STAGE(s, kt) do {                                             \
        uint32_t so = (uint32_t)(s) * GST32;                                   \
        int ko = (kt) * 32;                                                    \
        _Pragma("unroll")                                                      \
        for (int it = 0; it < 2; it++) {                                       \
            CPA16(dst[it] + so,         sA[it] + ko);                          \
            CPA16(dst[it] + so + 8192,  sA[it] + dAl + ko);                    \
            CPA16(dst[it] + so + 16384, sB[it] + ko);                          \
            CPA16(dst[it] + so + 24576, sB[it] + dBl + ko);                    \
        }                                                                      \
        asm volatile("cp.async.commit_group;");                                \
    } while (0)

    LOAD_STAGE(0, 0);
    LOAD_STAGE(1, 1);
    LOAD_STAGE(2, 2);

    float acc[2][8][4];
    #pragma unroll
    for (int i = 0; i < 2; i++)
        #pragma unroll
        for (int j = 0; j < 8; j++)
            #pragma unroll
            for (int q = 0; q < 4; q++) acc[i][j][q] = 0.f;

    const int frow = lane & 15;
    const int fhi  = lane >> 4;

    for (int kt = 0; kt < NT; kt++) {
        int s = kt % 3;
        asm volatile("cp.async.wait_group 2;" ::: "memory");
        __syncthreads();

        uint32_t ab = sbase + s * GST32;

        #pragma unroll
        for (int ks = 0; ks < 2; ks++) {
            int c = ks * 2 + fhi;
            uint32_t ah[2][4], al[2][4];
            #pragma unroll
            for (int i = 0; i < 2; i++) {
                uint32_t sw = sw64(wm * 32 + i * 16 + frow, c);
                ldsm_x4(ah[i], ab + sw);
                ldsm_x4(al[i], ab + 8192 + sw);
            }
            #pragma unroll
            for (int g = 0; g < 4; g++) {
                uint32_t bh[4], bl[4];
                uint32_t sw = sw64(wn * 64 + g * 16 + frow, c);
                ldsm_x4(bh, ab + 16384 + sw);
                ldsm_x4(bl, ab + 24576 + sw);
                #pragma unroll
                for (int i = 0; i < 2; i++)
                    #pragma unroll
                    for (int p = 0; p < 2; p++) {
                        mma_16816(acc[i][g*2+p], ah[i], bh[p], bh[p+2]);
                        mma_16816(acc[i][g*2+p], al[i], bh[p], bh[p+2]);
                        mma_16816(acc[i][g*2+p], ah[i], bl[p], bl[p+2]);
                    }
            }
        }
        __syncthreads();
        if (kt + 3 < NT) { LOAD_STAGE(s, kt + 3); }
        else { asm volatile("cp.async.commit_group;"); }
    }

    const int erow = lane >> 2;
    const int ecol = (lane & 3) * 2;
    if (mode == 0) {
        #pragma unroll
        for (int i = 0; i < 2; i++) {
            int r0 = brow + wm * 32 + i * 16 + erow;
            #pragma unroll
            for (int j = 0; j < 8; j++) {
                int cc = bcol + wn * 64 + j * 8 + ecol;
                *(float2*)(Cf + (size_t)r0 * N + cc) =
                    make_float2(acc[i][j][0], acc[i][j][1]);
                *(float2*)(Cf + (size_t)(r0 + 8) * N + cc) =
                    make_float2(acc[i][j][2], acc[i][j][3]);
            }
        }
    } else {
        const bool isq = (bcol < EMB);
        const float sc = isq ? scale : 1.0f;
        #pragma unroll
        for (int i = 0; i < 2; i++) {
            int r0 = brow + wm * 32 + i * 16 + erow;
            #pragma unroll
            for (int j = 0; j < 8; j++) {
                int cc = bcol + wn * 64 + j * 8 + ecol;
                #pragma unroll
                for (int half = 0; half < 2; half++) {
                    int r = r0 + half * 8;
                    float v0 = acc[i][j][half*2]   * sc;
                    float v1 = acc[i][j][half*2+1] * sc;
                    __nv_bfloat16 h0 = __float2bfloat16(v0);
                    __nv_bfloat16 h1 = __float2bfloat16(v1);
                    __nv_bfloat162 th, tl;
                    th.x = h0; th.y = h1;
                    tl.x = __float2bfloat16(v0 - __bfloat162float(h0));
                    tl.y = __float2bfloat16(v1 - __bfloat162float(h1));
                    if (isq) {
                        size_t idx = (size_t)r * EMB + cc;
                        *(__nv_bfloat162*)(g_qh + idx) = th;
                        *(__nv_bfloat162*)(g_ql + idx) = tl;
                    } else {
                        size_t idx = (size_t)r * KVS + (cc - EMB);
                        *(__nv_bfloat162*)(g_kvh + idx) = th;
                        *(__nv_bfloat162*)(g_kvl + idx) = tl;
                    }
                }
            }
        }
    }
    #undef LOAD_STAGE
}

// ----------------------------------------------------------------------------
// HMMA flash attention, hi/lo split on QK and PV.
// K and V share one smem buffer (V loaded during softmax) -> 98KB -> 2 CTA/SM.
// ----------------------------------------------------------------------------
#define AQH 0
#define AQL 16384
#define AKVH 32768
#define AKVL 49152
#define APS 65536                     // fp32 scores 64 x 68 = 17408
#define APB (APS + 17408)             // P hi
#define APL (APB + 8192)              // P lo
#define AST (APL + 8192)              // stats
#define ATT_SMEM (AST + 64*4*3)       // 100096 B

__device__ __forceinline__ uint32_t sw256(int r, int c) {
    return (uint32_t)(r * 256 + (((c & 7) ^ (r & 7)) | (c & 8)) * 16);
}
__device__ __forceinline__ uint32_t sw128(int r, int c) {
    return (uint32_t)(r * 128 + ((c ^ (r & 7)) * 16));
}

__global__ __launch_bounds__(256, 2) void attn_mma()
{
    extern __shared__ __align__(1024) char smraw[];
    const uint32_t sb = (uint32_t)__cvta_generic_to_shared(smraw);
    float* Ps     = (float*)(smraw + APS);
    float* row_m  = (float*)(smraw + AST);
    float* row_l  = row_m + 64;
    float* row_cf = row_l + 64;

    const int tid  = threadIdx.x;
    const int warp = tid >> 5, lane = tid & 31;
    const int wm   = warp & 3, wn = warp >> 2;
    const int frow = lane & 15, fhi = lane >> 4;
    const int iq   = blockIdx.x;
    const int h    = blockIdx.y;
    const int b    = blockIdx.z;
    const int kvhead = h / (NH / NKV);

    {
        const __nv_bfloat16* qh = g_qh + ((size_t)(b * S_LEN + iq * 64)) * EMB + h * HD;
        const __nv_bfloat16* ql = g_ql + ((size_t)(b * S_LEN + iq * 64)) * EMB + h * HD;
        #pragma unroll
        for (int it = 0; it < 4; it++) {
            int id = it * 256 + tid;
            int r = id >> 4, c = id & 15;
            CPA16(sb + AQH + sw256(r, c), qh + (size_t)r * EMB + c * 8);
            CPA16(sb + AQL + sw256(r, c), ql + (size_t)r * EMB + c * 8);
        }
        asm volatile("cp.async.commit_group;");
    }
    if (tid < 64) { row_m[tid] = -3.0e38f; row_l[tid] = 0.f; }

    float o[8][4];
    #pragma unroll
    for (int j = 0; j < 8; j++)
        #pragma unroll
        for (int q = 0; q < 4; q++) o[j][q] = 0.f;

    asm volatile("cp.async.wait_group 0;" ::: "memory");
    __syncthreads();

    const __nv_bfloat16* khb = g_kvh + ((size_t)(b * S_LEN)) * KVS + kvhead * HD;
    const __nv_bfloat16* klb = g_kvl + ((size_t)(b * S_LEN)) * KVS + kvhead * HD;
    const __nv_bfloat16* vhb = khb + KVDIM;
    const __nv_bfloat16* vlb = klb + KVDIM;

    for (int jt = 0; jt <= iq; jt++) {
        // ---- load K hi/lo into shared KV buffer ----
        {
            const __nv_bfloat16* kh = khb + (size_t)(jt * 64) * KVS;
            const __nv_bfloat16* kl = klb + (size_t)(jt * 64) * KVS;
            #pragma unroll
            for (int it = 0; it < 4; it++) {
                int id = it * 256 + tid;
                int r = id >> 4, c = id & 15;
                CPA16(sb + AKVH + sw256(r, c), kh + (size_t)r * KVS + c * 8);
                CPA16(sb + AKVL + sw256(r, c), kl + (size_t)r * KVS + c * 8);
            }
            asm volatile("cp.async.commit_group;");
            asm volatile("cp.async.wait_group 0;" ::: "memory");
            __syncthreads();
        }

        // ---- QK^T with 3-term split ----
        float sc[4][4];
        #pragma unroll
        for (int j = 0; j < 4; j++)
            #pragma unroll
            for (int q = 0; q < 4; q++) sc[j][q] = 0.f;

        #pragma unroll
        for (int ks = 0; ks < 8; ks++) {
            int c = ks * 2 + fhi;
            uint32_t ah[4], al[4];
            ldsm_x4(ah, sb + AQH + sw256(wm * 16 + frow, c));
            ldsm_x4(al, sb + AQL + sw256(wm * 16 + frow, c));
            #pragma unroll
            for (int g = 0; g < 2; g++) {
                uint32_t bh[4], bl[4];
                ldsm_x4(bh, sb + AKVH + sw256(wn * 32 + g * 16 + frow, c));
                ldsm_x4(bl, sb + AKVL + sw256(wn * 32 + g * 16 + frow, c));
                mma_16816(sc[g*2],   ah, bh[0], bh[2]);
                mma_16816(sc[g*2],   al, bh[0], bh[2]);
                mma_16816(sc[g*2],   ah, bl[0], bl[2]);
                mma_16816(sc[g*2+1], ah, bh[1], bh[3]);
                mma_16816(sc[g*2+1], al, bh[1], bh[3]);
                mma_16816(sc[g*2+1], ah, bl[1], bl[3]);
            }
        }

        // ---- scores -> smem fp32 ----
        {
            int r0 = wm * 16 + (lane >> 2);
            #pragma unroll
            for (int j = 0; j < 4; j++) {
                int col = wn * 32 + j * 8 + (lane & 3) * 2;
                *(float2*)(Ps + r0 * 68 + col)       = make_float2(sc[j][0], sc[j][1]);
                *(float2*)(Ps + (r0 + 8) * 68 + col) = make_float2(sc[j][2], sc[j][3]);
            }
        }
        __syncthreads();   // scores visible; all warps done reading K buffer

        // ---- issue V hi/lo load into the same KV buffer (overlaps softmax) ----
        {
            const __nv_bfloat16* vh = vhb + (size_t)(jt * 64) * KVS;
            const __nv_bfloat16* vl = vlb + (size_t)(jt * 64) * KVS;
            #pragma unroll
            for (int it = 0; it < 4; it++) {
                int id = it * 256 + tid;
                int r = id >> 4, c = id & 15;
                CPA16(sb + AKVH + sw256(r, c), vh + (size_t)r * KVS + c * 8);
                CPA16(sb + AKVL + sw256(r, c), vl + (size_t)r * KVS + c * 8);
            }
            asm volatile("cp.async.commit_group;");
        }

        // ---- online softmax: 4 threads/row; P -> hi/lo bf16 tiles ----
        {
            int r = tid >> 2, seg = tid & 3;
            float p[16];
            #pragma unroll
            for (int i4 = 0; i4 < 4; i4++) {
                float4 v = *(float4*)(Ps + r * 68 + seg * 16 + i4 * 4);
                p[i4*4+0] = v.x; p[i4*4+1] = v.y; p[i4*4+2] = v.z; p[i4*4+3] = v.w;
            }
            if (jt == iq) {
                #pragma unroll
                for (int i = 0; i < 16; i++)
                    if (seg * 16 + i > r) p[i] = -3.0e38f;
            }
            float mx = p[0];
            #pragma unroll
            for (int i = 1; i < 16; i++) mx = fmaxf(mx, p[i]);
            mx = fmaxf(mx, __shfl_xor_sync(0xFFFFFFFF, mx, 1));
            mx = fmaxf(mx, __shfl_xor_sync(0xFFFFFFFF, mx, 2));
            float m_old = row_m[r];
            float mnew = fmaxf(m_old, mx);
            float cf = __expf(m_old - mnew);
            float sum = 0.f;
            #pragma unroll
            for (int i = 0; i < 16; i++) { p[i] = __expf(p[i] - mnew); sum += p[i]; }
            sum += __shfl_xor_sync(0xFFFFFFFF, sum, 1);
            sum += __shfl_xor_sync(0xFFFFFFFF, sum, 2);
            if ((tid & 3) == 0) {
                row_m[r] = mnew;
                row_l[r] = row_l[r] * cf + sum;
                row_cf[r] = cf;
            }
            uint32_t ph[8], pl[8];
            #pragma unroll
            for (int i = 0; i < 8; i++) {
                __nv_bfloat16 h0 = __float2bfloat16(p[i*2]);
                __nv_bfloat16 h1 = __float2bfloat16(p[i*2+1]);
                __nv_bfloat162 th, tl;
                th.x = h0; th.y = h1;
                tl.x = __float2bfloat16(p[i*2]   - __bfloat162float(h0));
                tl.y = __float2bfloat16(p[i*2+1] - __bfloat162float(h1));
                ph[i] = *(uint32_t*)&th;
                pl[i] = *(uint32_t*)&tl;
            }
            uint32_t d0 = sb + APB + sw128(r, seg * 2);
            uint32_t d1 = sb + APB + sw128(r, seg * 2 + 1);
            uint32_t e0 = sb + APL + sw128(r, seg * 2);
            uint32_t e1 = sb + APL + sw128(r, seg * 2 + 1);
            asm volatile("st.shared.v4.b32 [%0], {%1,%2,%3,%4};"
                         :: "r"(d0), "r"(ph[0]), "r"(ph[1]), "r"(ph[2]), "r"(ph[3]));
            asm volatile("st.shared.v4.b32 [%0], {%1,%2,%3,%4};"
                         :: "r"(d1), "r"(ph[4]), "r"(ph[5]), "r"(ph[6]), "r"(ph[7]));
            asm volatile("st.shared.v4.b32 [%0], {%1,%2,%3,%4};"
                         :: "r"(e0), "r"(pl[0]), "r"(pl[1]), "r"(pl[2]), "r"(pl[3]));
            asm volatile("st.shared.v4.b32 [%0], {%1,%2,%3,%4};"
                         :: "r"(e1), "r"(pl[4]), "r"(pl[5]), "r"(pl[6]), "r"(pl[7]));
        }
        asm volatile("cp.async.wait_group 0;" ::: "memory");
        __syncthreads();   // P tiles + V tiles both ready

        // ---- rescale O, then O += P @ V with 3-term split ----
        {
            float cf0 = row_cf[wm * 16 + (lane >> 2)];
            float cf1 = row_cf[wm * 16 + 8 + (lane >> 2)];
            #pragma unroll
            for (int j = 0; j < 8; j++) {
                o[j][0] *= cf0; o[j][1] *= cf0;
                o[j][2] *= cf1; o[j][3] *= cf1;
            }
        }
        #pragma unroll
        for (int kc = 0; kc < 4; kc++) {
            uint32_t aph[4], apl[4];
            ldsm_x4(aph, sb + APB + sw128(wm * 16 + frow, kc * 2 + fhi));
            ldsm_x4(apl, sb + APL + sw128(wm * 16 + frow, kc * 2 + fhi));
            int t  = kc * 16 + ((lane >> 3) & 1) * 8 + (lane & 7);
            int cd = ((wn * 64) >> 3) + (lane >> 4);
            #pragma unroll
            for (int g = 0; g < 4; g++) {
                uint32_t bvh[4], bvl[4];
                ldsm_x4_t(bvh, sb + AKVH + sw256(t, cd + g * 2));
                ldsm_x4_t(bvl, sb + AKVL + sw256(t, cd + g * 2));
                mma_16816(o[g*2],   aph, bvh[0], bvh[1]);
                mma_16816(o[g*2],   apl, bvh[0], bvh[1]);
                mma_16816(o[g*2],   aph, bvl[0], bvl[1]);
                mma_16816(o[g*2+1], aph, bvh[2], bvh[3]);
                mma_16816(o[g*2+1], apl, bvh[2], bvh[3]);
                mma_16816(o[g*2+1], aph, bvl[2], bvl[3]);
            }
        }
        __syncthreads();   // done with V + P before next K load
    }

    // ---- epilogue: normalize + bf16 hi/lo write ----
    {
        int rr = lane >> 2;
        float invl0 = 1.f / row_l[wm * 16 + rr];
        float invl1 = 1.f / row_l[wm * 16 + 8 + rr];
        size_t base = ((size_t)(b * S_LEN + iq * 64 + wm * 16 + rr)) * EMB + h * HD;
        #pragma unroll
        for (int j = 0; j < 8; j++) {
            int col = wn * 64 + j * 8 + (lane & 3) * 2;
            float v0 = o[j][0] * invl0, v1 = o[j][1] * invl0;
            float v2 = o[j][2] * invl1, v3 = o[j][3] * invl1;
            __nv_bfloat16 h0 = __float2bfloat16(v0), h1 = __float2bfloat16(v1);
            __nv_bfloat16 h2 = __float2bfloat16(v2), h3 = __float2bfloat16(v3);
            __nv_bfloat162 th0, th1, tl0, tl1;
            th0.x = h0; th0.y = h1; th1.x = h2; th1.y = h3;
            tl0.x = __float2bfloat16(v0 - __bfloat162float(h0));
            tl0.y = __float2bfloat16(v1 - __bfloat162float(h1));
            tl1.x = __float2bfloat16(v2 - __bfloat162float(h2));
            tl1.y = __float2bfloat16(v3 - __bfloat162float(h3));
            *(__nv_bfloat162*)(g_ah + base + col)           = th0;
            *(__nv_bfloat162*)(g_al + base + col)           = tl0;
            *(__nv_bfloat162*)(g_ah + base + 8*EMB + col)   = th1;
            *(__nv_bfloat162*)(g_al + base + 8*EMB + col)   = tl1;
        }
    }
}

// ----------------------------------------------------------------------------
// Launch
// ----------------------------------------------------------------------------
extern "C" void kernel_launch(void* const* d_in, const int* in_sizes, int n_in,
                              void* d_out, int out_size)
{
    const float* x  = (const float*)d_in[0];
    const float* Wq = (const float*)d_in[1];
    const float* Wk = (const float*)d_in[2];
    const float* Wv = (const float*)d_in[3];
    const float* Wo = (const float*)d_in[4];
    float* out = (float*)d_out;

    __nv_bfloat16 *xh, *xl, *wh, *wl, *woh, *wol, *ah, *al;
    cudaGetSymbolAddress((void**)&xh, g_xh);
    cudaGetSymbolAddress((void**)&xl, g_xl);
    cudaGetSymbolAddress((void**)&wh, g_wh);
    cudaGetSymbolAddress((void**)&wl, g_wl);
    cudaGetSymbolAddress((void**)&woh, g_woh);
    cudaGetSymbolAddress((void**)&wol, g_wol);
    cudaGetSymbolAddress((void**)&ah, g_ah);
    cudaGetSymbolAddress((void**)&al, g_al);

    cudaFuncSetAttribute(gemm_hl, cudaFuncAttributeMaxDynamicSharedMemorySize, GEMM_SMEM);
    cudaFuncSetAttribute(attn_mma, cudaFuncAttributeMaxDynamicSharedMemorySize, ATT_SMEM);

    // splits: x; [Wq|Wk|Wv] into combined wh/wl; Wo
    {
        int t8 = MROWS * EMB / 8;
        split2v<<<t8 / 256, 256>>>(x, xh, xl, t8);
        t8 = EMB * EMB / 8;
        split2v<<<t8 / 256, 256>>>(Wq, wh, wl, t8);
        split2v<<<t8 / 256, 256>>>(Wo, woh, wol, t8);
        t8 = KVDIM * EMB / 8;
        split2v<<<t8 / 256, 256>>>(Wk, wh + (size_t)EMB * EMB,
                                       wl + (size_t)EMB * EMB, t8);
        split2v<<<t8 / 256, 256>>>(Wv, wh + (size_t)(EMB + KVDIM) * EMB,
                                       wl + (size_t)(EMB + KVDIM) * EMB, t8);
    }

    const float qscale = 0.08838834764831845f;  // 1/sqrt(128)

    // fused QKV projection (N = 3072)
    dim3 gqkv(QKVN / 128, MROWS / 128);   // (24, 32)
    gemm_hl<<<gqkv, 256, GEMM_SMEM>>>(xh, xl, wh, wl, nullptr, 1, qscale,
                                      MROWS, QKVN, EMB);

    dim3 ga(S_LEN / 64, NH, BATCH);       // (32, 16, 2)
    attn_mma<<<ga, 256, ATT_SMEM>>>();

    // O projection -> fp32 out
    dim3 go(EMB / 128, MROWS / 128);      // (16, 32)
    gemm_hl<<<go, 256, GEMM_SMEM>>>(ah, al, woh, wol, out, 0, 1.0f,
                                    MROWS, EMB, EMB);
}

// round 9
// speedup vs baseline: 3.5820x; 1.0030x over previous
#include <cuda_runtime.h>
#include <cuda_bf16.h>
#include <cstdint>
#include <math.h>

#define S_LEN 2048
#define BATCH 2
#define EMB   2048
#define NH    16
#define NKV   4
#define HD    128
#define KVDIM (NKV*HD)        // 512
#define KVS   (2*KVDIM)       // 1024
#define QKVN  (EMB + KVS)     // 3072
#define MROWS (BATCH*S_LEN)   // 4096

// ---------------- scratch (allocation-free) ----------------
__device__ __nv_bfloat16 g_xh[(size_t)MROWS * EMB];
__device__ __nv_bfloat16 g_xl[(size_t)MROWS * EMB];
__device__ __nv_bfloat16 g_wh[(size_t)QKVN * EMB];    // [Wq | Wk | Wv] hi
__device__ __nv_bfloat16 g_wl[(size_t)QKVN * EMB];
__device__ __nv_bfloat16 g_woh[(size_t)EMB * EMB];
__device__ __nv_bfloat16 g_wol[(size_t)EMB * EMB];
__device__ __nv_bfloat16 g_qh[(size_t)MROWS * EMB];
__device__ __nv_bfloat16 g_ql[(size_t)MROWS * EMB];
__device__ __nv_bfloat16 g_kvh[(size_t)MROWS * KVS];
__device__ __nv_bfloat16 g_kvl[(size_t)MROWS * KVS];
__device__ __nv_bfloat16 g_ah[(size_t)MROWS * EMB];
__device__ __nv_bfloat16 g_al[(size_t)MROWS * EMB];

// ---------------- common MMA helpers ----------------
__device__ __forceinline__ void ldsm_x4(uint32_t* r, uint32_t addr) {
    asm volatile("ldmatrix.sync.aligned.m8n8.x4.shared.b16 {%0,%1,%2,%3}, [%4];"
                 : "=r"(r[0]), "=r"(r[1]), "=r"(r[2]), "=r"(r[3]) : "r"(addr));
}
__device__ __forceinline__ void ldsm_x4_t(uint32_t* r, uint32_t addr) {
    asm volatile("ldmatrix.sync.aligned.m8n8.x4.trans.shared.b16 {%0,%1,%2,%3}, [%4];"
                 : "=r"(r[0]), "=r"(r[1]), "=r"(r[2]), "=r"(r[3]) : "r"(addr));
}
__device__ __forceinline__ void mma_16816(float* d, const uint32_t* a, uint32_t b0,
                                          uint32_t b1) {
    asm volatile(
        "mma.sync.aligned.m16n8k16.row.col.f32.bf16.bf16.f32 "
        "{%0,%1,%2,%3}, {%4,%5,%6,%7}, {%8,%9}, {%0,%1,%2,%3};"
        : "+f"(d[0]), "+f"(d[1]), "+f"(d[2]), "+f"(d[3])
        : "r"(a[0]), "r"(a[1]), "r"(a[2]), "r"(a[3]), "r"(b0), "r"(b1));
}
#define CPA16(dst, src) \
    asm volatile("cp.async.cg.shared.global [%0], [%1], 16;" :: "r"(dst), "l"(src))

__device__ __forceinline__ void split_pack(float v0, float v1,
                                           uint32_t& H, uint32_t& L) {
    __nv_bfloat16 h0 = __float2bfloat16(v0);
    __nv_bfloat16 h1 = __float2bfloat16(v1);
    __nv_bfloat162 th, tl;
    th.x = h0; th.y = h1;
    tl.x = __float2bfloat16(v0 - __bfloat162float(h0));
    tl.y = __float2bfloat16(v1 - __bfloat162float(h1));
    H = *(uint32_t*)&th;
    L = *(uint32_t*)&tl;
}

// ----------------------------------------------------------------------------
// ONE split kernel for all 5 input tensors (x, Wq, Wk, Wv, Wo)
// unit = 8 floats.  x:1048576  Wq:524288  Wk:131072  Wv:131072  Wo:524288
// ----------------------------------------------------------------------------
#define UX   1048576
#define UWQ  (UX + 524288)
#define UWK  (UWQ + 131072)
#define UWV  (UWK + 131072)
#define UTOT (UWV + 524288)     // 2359296 units -> 9216 blocks

__global__ __launch_bounds__(256) void split_all(
    const float* __restrict__ x,  const float* __restrict__ Wq,
    const float* __restrict__ Wk, const float* __restrict__ Wv,
    const float* __restrict__ Wo)
{
    int i = blockIdx.x * blockDim.x + threadIdx.x;
    if (i >= UTOT) return;
    const float* src;
    __nv_bfloat16 *hi, *lo;
    size_t off;
    if (i < UX)        { src = x;  hi = g_xh;  lo = g_xl;  off = (size_t)i; }
    else if (i < UWQ)  { src = Wq; hi = g_wh;  lo = g_wl;  off = (size_t)(i - UX); }
    else if (i < UWK)  { src = Wk; hi = g_wh + (size_t)EMB*EMB; lo = g_wl + (size_t)EMB*EMB; off = (size_t)(i - UWQ); }
    else if (i < UWV)  { src = Wv; hi = g_wh + (size_t)(EMB+KVDIM)*EMB; lo = g_wl + (size_t)(EMB+KVDIM)*EMB; off = (size_t)(i - UWK); }
    else               { src = Wo; hi = g_woh; lo = g_wol; off = (size_t)(i - UWV); }

    const float4* p = (const float4*)(src + off * 8);
    float4 a = p[0], b = p[1];
    float f[8] = {a.x, a.y, a.z, a.w, b.x, b.y, b.z, b.w};
    uint32_t H[4], L[4];
    #pragma unroll
    for (int j = 0; j < 4; j++) split_pack(f[j*2], f[j*2+1], H[j], L[j]);
    *(uint4*)(hi + off * 8) = make_uint4(H[0], H[1], H[2], H[3]);
    *(uint4*)(lo + off * 8) = make_uint4(L[0], L[1], L[2], L[3]);
}

// ----------------------------------------------------------------------------
// hi/lo HMMA GEMM, BK=32, 3 stages x 32KB, 2 CTAs/SM (unchanged from R8).
// ----------------------------------------------------------------------------
#define GST32 32768
#define GEMM_SMEM (3 * GST32)

__device__ __forceinline__ uint32_t sw64(int r, int c) {
    return (uint32_t)(r * 64 + ((c ^ ((r >> 1) & 3)) * 16));
}

__global__ __launch_bounds__(256, 2) void gemm_hl(
    const __nv_bfloat16* __restrict__ Ah, const __nv_bfloat16* __restrict__ Al,
    const __nv_bfloat16* __restrict__ Bh, const __nv_bfloat16* __restrict__ Bl,
    float* __restrict__ Cf, int mode, float scale, int M, int N, int K)
{
    extern __shared__ __align__(1024) char smem[];
    const uint32_t sbase = (uint32_t)__cvta_generic_to_shared(smem);

    const int tid  = threadIdx.x;
    const int warp = tid >> 5, lane = tid & 31;
    const int wm   = warp & 3, wn = warp >> 2;
    const int brow = blockIdx.y * 128, bcol = blockIdx.x * 128;

    const size_t dAl = (size_t)(Al - Ah);
    const size_t dBl = (size_t)(Bl - Bh);

    uint32_t dst[2];
    const __nv_bfloat16* sA[2];
    const __nv_bfloat16* sB[2];
    #pragma unroll
    for (int it = 0; it < 2; it++) {
        int id  = it * 256 + tid;
        int row = id >> 2, c = id & 3;
        dst[it] = sbase + sw64(row, c);
        sA[it]  = Ah + (size_t)(brow + row) * K + c * 8;
        sB[it]  = Bh + (size_t)(bcol + row) * K + c * 8;
    }

    const int NT = K / 32;

    #define LOAD_STAGE(s, kt) do {                                             \
        uint32_t so = (uint32_t)(s) * GST32;                                   \
        int ko = (kt) * 32;                                                    \
        _Pragma("unroll")                                                      \
        for (int it = 0; it < 2; it++) {                                       \
            CPA16(dst[it] + so,         sA[it] + ko);                          \
            CPA16(dst[it] + so + 8192,  sA[it] + dAl + ko);                    \
            CPA16(dst[it] + so + 16384, sB[it] + ko);                          \
            CPA16(dst[it] + so + 24576, sB[it] + dBl + ko);                    \
        }                                                                      \
        asm volatile("cp.async.commit_group;");                                \
    } while (0)

    LOAD_STAGE(0, 0);
    LOAD_STAGE(1, 1);
    LOAD_STAGE(2, 2);

    float acc[2][8][4];
    #pragma unroll
    for (int i = 0; i < 2; i++)
        #pragma unroll
        for (int j = 0; j < 8; j++)
            #pragma unroll
            for (int q = 0; q < 4; q++) acc[i][j][q] = 0.f;

    const int frow = lane & 15;
    const int fhi  = lane >> 4;

    for (int kt = 0; kt < NT; kt++) {
        int s = kt % 3;
        asm volatile("cp.async.wait_group 2;" ::: "memory");
        __syncthreads();

        uint32_t ab = sbase + s * GST32;

        #pragma unroll
        for (int ks = 0; ks < 2; ks++) {
            int c = ks * 2 + fhi;
            uint32_t ah[2][4], al[2][4];
            #pragma unroll
            for (int i = 0; i < 2; i++) {
                uint32_t sw = sw64(wm * 32 + i * 16 + frow, c);
                ldsm_x4(ah[i], ab + sw);
                ldsm_x4(al[i], ab + 8192 + sw);
            }
            #pragma unroll
            for (int g = 0; g < 4; g++) {
                uint32_t bh[4], bl[4];
                uint32_t sw = sw64(wn * 64 + g * 16 + frow, c);
                ldsm_x4(bh, ab + 16384 + sw);
                ldsm_x4(bl, ab + 24576 + sw);
                #pragma unroll
                for (int i = 0; i < 2; i++)
                    #pragma unroll
                    for (int p = 0; p < 2; p++) {
                        mma_16816(acc[i][g*2+p], ah[i], bh[p], bh[p+2]);
                        mma_16816(acc[i][g*2+p], al[i], bh[p], bh[p+2]);
                        mma_16816(acc[i][g*2+p], ah[i], bl[p], bl[p+2]);
                    }
            }
        }
        __syncthreads();
        if (kt + 3 < NT) { LOAD_STAGE(s, kt + 3); }
        else { asm volatile("cp.async.commit_group;"); }
    }

    const int erow = lane >> 2;
    const int ecol = (lane & 3) * 2;
    if (mode == 0) {
        #pragma unroll
        for (int i = 0; i < 2; i++) {
            int r0 = brow + wm * 32 + i * 16 + erow;
            #pragma unroll
            for (int j = 0; j < 8; j++) {
                int cc = bcol + wn * 64 + j * 8 + ecol;
                *(float2*)(Cf + (size_t)r0 * N + cc) =
                    make_float2(acc[i][j][0], acc[i][j][1]);
                *(float2*)(Cf + (size_t)(r0 + 8) * N + cc) =
                    make_float2(acc[i][j][2], acc[i][j][3]);
            }
        }
    } else {
        const bool isq = (bcol < EMB);
        const float sc = isq ? scale : 1.0f;
        #pragma unroll
        for (int i = 0; i < 2; i++) {
            int r0 = brow + wm * 32 + i * 16 + erow;
            #pragma unroll
            for (int j = 0; j < 8; j++) {
                int cc = bcol + wn * 64 + j * 8 + ecol;
                #pragma unroll
                for (int half = 0; half < 2; half++) {
                    int r = r0 + half * 8;
                    uint32_t H, L;
                    split_pack(acc[i][j][half*2] * sc, acc[i][j][half*2+1] * sc, H, L);
                    if (isq) {
                        size_t idx = (size_t)r * EMB + cc;
                        *(uint32_t*)(g_qh + idx) = H;
                        *(uint32_t*)(g_ql + idx) = L;
                    } else {
                        size_t idx = (size_t)r * KVS + (cc - EMB);
                        *(uint32_t*)(g_kvh + idx) = H;
                        *(uint32_t*)(g_kvl + idx) = L;
                    }
                }
            }
        }
    }
    #undef LOAD_STAGE
}

// ----------------------------------------------------------------------------
// FA2-style HMMA flash attention: 128 threads, warp owns 16 full rows.
// Softmax + stats + P hi/lo all in registers. smem = Q(32K) + KV(32K) = 64KB
// -> 3 CTAs/SM. hi/lo 3-term split on QK and PV.
// ----------------------------------------------------------------------------
#define AQH 0
#define AQL 16384
#define AKVH 32768
#define AKVL 49152
#define ATT_SMEM 65536

__device__ __forceinline__ uint32_t sw256(int r, int c) {
    return (uint32_t)(r * 256 + (((c & 7) ^ (r & 7)) | (c & 8)) * 16);
}

__global__ __launch_bounds__(128, 3) void attn_mma()
{
    extern __shared__ __align__(1024) char smraw[];
    const uint32_t sb = (uint32_t)__cvta_generic_to_shared(smraw);

    const int tid  = threadIdx.x;
    const int wm   = tid >> 5, lane = tid & 31;
    const int frow = lane & 15, fhi = lane >> 4;
    const int q    = lane >> 2, tc = lane & 3;
    const int iq   = blockIdx.x;
    const int h    = blockIdx.y;
    const int b    = blockIdx.z;
    const int kvhead = h / (NH / NKV);

    // ---- Q hi/lo load (64 x 128) ----
    {
        const __nv_bfloat16* qh = g_qh + ((size_t)(b * S_LEN + iq * 64)) * EMB + h * HD;
        const __nv_bfloat16* ql = g_ql + ((size_t)(b * S_LEN + iq * 64)) * EMB + h * HD;
        #pragma unroll
        for (int it = 0; it < 8; it++) {
            int id = it * 128 + tid;
            int r = id >> 4, c = id & 15;
            CPA16(sb + AQH + sw256(r, c), qh + (size_t)r * EMB + c * 8);
            CPA16(sb + AQL + sw256(r, c), ql + (size_t)r * EMB + c * 8);
        }
        asm volatile("cp.async.commit_group;");
    }

    float o[16][4];
    #pragma unroll
    for (int j = 0; j < 16; j++)
        #pragma unroll
        for (int e = 0; e < 4; e++) o[j][e] = 0.f;
    float m0 = -3.0e38f, m1 = -3.0e38f, l0 = 0.f, l1 = 0.f;

    const __nv_bfloat16* khb = g_kvh + ((size_t)(b * S_LEN)) * KVS + kvhead * HD;
    const __nv_bfloat16* klb = g_kvl + ((size_t)(b * S_LEN)) * KVS + kvhead * HD;

    for (int jt = 0; jt <= iq; jt++) {
        __syncthreads();   // prev V readers done (and nothing pending first iter)
        // ---- K hi/lo load ----
        {
            const __nv_bfloat16* kh = khb + (size_t)(jt * 64) * KVS;
            const __nv_bfloat16* kl = klb + (size_t)(jt * 64) * KVS;
            #pragma unroll
            for (int it = 0; it < 8; it++) {
                int id = it * 128 + tid;
                int r = id >> 4, c = id & 15;
                CPA16(sb + AKVH + sw256(r, c), kh + (size_t)r * KVS + c * 8);
                CPA16(sb + AKVL + sw256(r, c), kl + (size_t)r * KVS + c * 8);
            }
            asm volatile("cp.async.commit_group;");
            asm volatile("cp.async.wait_group 0;" ::: "memory");
            __syncthreads();
        }

        // ---- QK^T, 3-term, warp covers 16 rows x 64 cols ----
        float sc[8][4];
        #pragma unroll
        for (int j = 0; j < 8; j++)
            #pragma unroll
            for (int e = 0; e < 4; e++) sc[j][e] = 0.f;

        #pragma unroll
        for (int ks = 0; ks < 8; ks++) {
            int c = ks * 2 + fhi;
            uint32_t ah[4], al[4];
            ldsm_x4(ah, sb + AQH + sw256(wm * 16 + frow, c));
            ldsm_x4(al, sb + AQL + sw256(wm * 16 + frow, c));
            #pragma unroll
            for (int g = 0; g < 4; g++) {
                uint32_t bh[4], bl[4];
                ldsm_x4(bh, sb + AKVH + sw256(g * 16 + frow, c));
                ldsm_x4(bl, sb + AKVL + sw256(g * 16 + frow, c));
                mma_16816(sc[g*2],   ah, bh[0], bh[2]);
                mma_16816(sc[g*2],   al, bh[0], bh[2]);
                mma_16816(sc[g*2],   ah, bl[0], bl[2]);
                mma_16816(sc[g*2+1], ah, bh[1], bh[3]);
                mma_16816(sc[g*2+1], al, bh[1], bh[3]);
                mma_16816(sc[g*2+1], ah, bl[1], bl[3]);
            }
        }
        __syncthreads();   // all warps done reading K smem

        // ---- V hi/lo load into same buffer (overlaps softmax) ----
        {
            const __nv_bfloat16* vh = khb + KVDIM + (size_t)(jt * 64) * KVS;
            const __nv_bfloat16* vl = klb + KVDIM + (size_t)(jt * 64) * KVS;
            #pragma unroll
            for (int it = 0; it < 8; it++) {
                int id = it * 128 + tid;
                int r = id >> 4, c = id & 15;
                CPA16(sb + AKVH + sw256(r, c), vh + (size_t)r * KVS + c * 8);
                CPA16(sb + AKVL + sw256(r, c), vl + (size_t)r * KVS + c * 8);
            }
            asm volatile("cp.async.commit_group;");
        }

        // ---- register softmax (rows q and q+8 of this warp's 16) ----
        if (jt == iq) {
            int r0 = wm * 16 + q, r1 = r0 + 8;
            #pragma unroll
            for (int j = 0; j < 8; j++) {
                int c0 = j * 8 + tc * 2;
                if (c0     > r0) sc[j][0] = -3.0e38f;
                if (c0 + 1 > r0) sc[j][1] = -3.0e38f;
                if (c0     > r1) sc[j][2] = -3.0e38f;
                if (c0 + 1 > r1) sc[j][3] = -3.0e38f;
            }
        }
        float mx0 = sc[0][0], mx1 = sc[0][2];
        #pragma unroll
        for (int j = 0; j < 8; j++) {
            mx0 = fmaxf(mx0, fmaxf(sc[j][0], sc[j][1]));
            mx1 = fmaxf(mx1, fmaxf(sc[j][2], sc[j][3]));
        }
        mx0 = fmaxf(mx0, __shfl_xor_sync(0xFFFFFFFF, mx0, 1));
        mx0 = fmaxf(mx0, __shfl_xor_sync(0xFFFFFFFF, mx0, 2));
        mx1 = fmaxf(mx1, __shfl_xor_sync(0xFFFFFFFF, mx1, 1));
        mx1 = fmaxf(mx1, __shfl_xor_sync(0xFFFFFFFF, mx1, 2));
        float mn0 = fmaxf(m0, mx0), mn1 = fmaxf(m1, mx1);
        float cf0 = __expf(m0 - mn0), cf1 = __expf(m1 - mn1);
        float s0 = 0.f, s1 = 0.f;
        #pragma unroll
        for (int j = 0; j < 8; j++) {
            sc[j][0] = __expf(sc[j][0] - mn0); s0 += sc[j][0];
            sc[j][1] = __expf(sc[j][1] - mn0); s0 += sc[j][1];
            sc[j][2] = __expf(sc[j][2] - mn1); s1 += sc[j][2];
            sc[j][3] = __expf(sc[j][3] - mn1); s1 += sc[j][3];
        }
        s0 += __shfl_xor_sync(0xFFFFFFFF, s0, 1);
        s0 += __shfl_xor_sync(0xFFFFFFFF, s0, 2);
        s1 += __shfl_xor_sync(0xFFFFFFFF, s1, 1);
        s1 += __shfl_xor_sync(0xFFFFFFFF, s1, 2);
        l0 = l0 * cf0 + s0;  l1 = l1 * cf1 + s1;
        m0 = mn0;  m1 = mn1;

        // rescale O
        #pragma unroll
        for (int j = 0; j < 16; j++) {
            o[j][0] *= cf0; o[j][1] *= cf0;
            o[j][2] *= cf1; o[j][3] *= cf1;
        }

        // pack P hi/lo in registers as A-fragments (kc = k16 chunk of kv dim)
        uint32_t ph[4][4], pl[4][4];
        #pragma unroll
        for (int kc = 0; kc < 4; kc++) {
            split_pack(sc[kc*2][0],   sc[kc*2][1],   ph[kc][0], pl[kc][0]);
            split_pack(sc[kc*2][2],   sc[kc*2][3],   ph[kc][1], pl[kc][1]);
            split_pack(sc[kc*2+1][0], sc[kc*2+1][1], ph[kc][2], pl[kc][2]);
            split_pack(sc[kc*2+1][2], sc[kc*2+1][3], ph[kc][3], pl[kc][3]);
        }

        asm volatile("cp.async.wait_group 0;" ::: "memory");
        __syncthreads();   // V ready

        // ---- O += P @ V, 3-term; warp covers its 16 rows x all 128 d ----
        int t = ((lane >> 3) & 1) * 8 + (lane & 7);
        #pragma unroll
        for (int kc = 0; kc < 4; kc++) {
            #pragma unroll
            for (int g = 0; g < 8; g++) {
                int cd = g * 2 + fhi;
                uint32_t bvh[4], bvl[4];
                ldsm_x4_t(bvh, sb + AKVH + sw256(kc * 16 + t, cd));
                ldsm_x4_t(bvl, sb + AKVL + sw256(kc * 16 + t, cd));
                mma_16816(o[g*2],   ph[kc], bvh[0], bvh[1]);
                mma_16816(o[g*2],   pl[kc], bvh[0], bvh[1]);
                mma_16816(o[g*2],   ph[kc], bvl[0], bvl[1]);
                mma_16816(o[g*2+1], ph[kc], bvh[2], bvh[3]);
                mma_16816(o[g*2+1], pl[kc], bvh[2], bvh[3]);
                mma_16816(o[g*2+1], ph[kc], bvl[2], bvl[3]);
            }
        }
    }

    // ---- epilogue: normalize + bf16 hi/lo write ----
    {
        float invl0 = 1.f / l0, invl1 = 1.f / l1;
        size_t base = ((size_t)(b * S_LEN + iq * 64 + wm * 16 + q)) * EMB + h * HD;
        #pragma unroll
        for (int j = 0; j < 16; j++) {
            int col = j * 8 + tc * 2;
            uint32_t H0, L0, H1, L1;
            split_pack(o[j][0] * invl0, o[j][1] * invl0, H0, L0);
            split_pack(o[j][2] * invl1, o[j][3] * invl1, H1, L1);
            *(uint32_t*)(g_ah + base + col)           = H0;
            *(uint32_t*)(g_al + base + col)           = L0;
            *(uint32_t*)(g_ah + base + 8*EMB + col)   = H1;
            *(uint32_t*)(g_al + base + 8*EMB + col)   = L1;
        }
    }
}

// ----------------------------------------------------------------------------
// Launch
// ----------------------------------------------------------------------------
extern "C" void kernel_launch(void* const* d_in, const int* in_sizes, int n_in,
                              void* d_out, int out_size)
{
    const float* x  = (const float*)d_in[0];
    const float* Wq = (const float*)d_in[1];
    const float* Wk = (const float*)d_in[2];
    const float* Wv = (const float*)d_in[3];
    const float* Wo = (const float*)d_in[4];
    float* out = (float*)d_out;

    __nv_bfloat16 *xh, *xl, *wh, *wl, *woh, *wol, *ah, *al;
    cudaGetSymbolAddress((void**)&xh, g_xh);
    cudaGetSymbolAddress((void**)&xl, g_xl);
    cudaGetSymbolAddress((void**)&wh, g_wh);
    cudaGetSymbolAddress((void**)&wl, g_wl);
    cudaGetSymbolAddress((void**)&woh, g_woh);
    cudaGetSymbolAddress((void**)&wol, g_wol);
    cudaGetSymbolAddress((void**)&ah, g_ah);
    cudaGetSymbolAddress((void**)&al, g_al);

    cudaFuncSetAttribute(gemm_hl, cudaFuncAttributeMaxDynamicSharedMemorySize, GEMM_SMEM);
    cudaFuncSetAttribute(attn_mma, cudaFuncAttributeMaxDynamicSharedMemorySize, ATT_SMEM);

    // one fused split for all inputs
    split_all<<<(UTOT + 255) / 256, 256>>>(x, Wq, Wk, Wv, Wo);

    const float qscale = 0.08838834764831845f;  // 1/sqrt(128)

    dim3 gqkv(QKVN / 128, MROWS / 128);   // (24, 32)
    gemm_hl<<<gqkv, 256, GEMM_SMEM>>>(xh, xl, wh, wl, nullptr, 1, qscale,
                                      MROWS, QKVN, EMB);

    dim3 ga(S_LEN / 64, NH, BATCH);       // (32, 16, 2)
    attn_mma<<<ga, 128, ATT_SMEM>>>();

    dim3 go(EMB / 128, MROWS / 128);      // (16, 32)
    gemm_hl<<<go, 256, GEMM_SMEM>>>(ah, al, woh, wol, out, 0, 1.0f,
                                    MROWS, EMB, EMB);
}